// round 6
// baseline (speedup 1.0000x reference)
#include <cuda_runtime.h>
#include <cuda_bf16.h>
#include <math.h>
#include <mma.h>
using namespace nvcuda;

// ---------------- problem constants ----------------
constexpr int CB  = 2;
constexpr int CS  = 1024;
constexpr int CD  = 2048;
constexpr int CH  = 16;
constexpr int CKVH= 4;
constexpr int CHD = 128;
constexpr int CE  = 64;
constexpr int CK  = 8;
constexpr int CF  = 768;
constexpr int CT  = CB * CS;             // 2048
constexpr float CEPS = 1e-6f;
constexpr int NSLOT = CT * CK;           // 16384
constexpr int PADTOT = NSLOT + CE * 128; // 24576

// ---------------- scratch ----------------
__device__ float g_h   [CT * CD];
__device__ float g_q   [CT * CH  * CHD];
__device__ float g_k   [CT * CKVH* CHD];
__device__ float g_v   [CT * CKVH* CHD];
__device__ float g_o   [CT * CH  * CHD];
__device__ float g_ht  [CT * CD];
__device__ __nv_bfloat16 g_ht_bf[CT * CD];
__device__ float g_logits[CT * CE];
__device__ int   g_topi[CT * CK];
__device__ float g_topw[CT * CK];
__device__ int   g_counts[CE];
__device__ int   g_offsets[CE];
__device__ int   g_cursor[CE];
__device__ int   g_slot_token[PADTOT];
__device__ int   g_pos_of[NSLOT];
__device__ float g_gate[(size_t)PADTOT * CF];
__device__ __nv_bfloat16 g_act_bf[(size_t)PADTOT * CF];
__device__ float g_y   [(size_t)PADTOT * CD];

// ---------------- helpers ----------------
__device__ __forceinline__ void st_bf4(__nv_bfloat16* p, float4 v) {
    __nv_bfloat162 lo = __floats2bfloat162_rn(v.x, v.y);
    __nv_bfloat162 hi = __floats2bfloat162_rn(v.z, v.w);
    uint2 u;
    u.x = *(unsigned int*)&lo;
    u.y = *(unsigned int*)&hi;
    *(uint2*)p = u;
}

// ---------------- rmsnorm ----------------
__global__ void rmsnorm_kernel(const float* __restrict__ in,
                               const float* __restrict__ w,
                               float* __restrict__ out) {
    int t = blockIdx.x;
    const float* row = in + (size_t)t * CD;
    float ss = 0.f;
    for (int d = threadIdx.x; d < CD; d += 256) { float v = row[d]; ss += v * v; }
    __shared__ float red[256];
    red[threadIdx.x] = ss; __syncthreads();
    for (int st = 128; st > 0; st >>= 1) {
        if (threadIdx.x < st) red[threadIdx.x] += red[threadIdx.x + st];
        __syncthreads();
    }
    float scale = rsqrtf(red[0] / (float)CD + CEPS);
    for (int d = threadIdx.x; d < CD; d += 256)
        out[(size_t)t * CD + d] = row[d] * scale * w[d];
}

__global__ void rmsnorm_bf_kernel(const float* __restrict__ in,
                                  const float* __restrict__ w,
                                  float* __restrict__ out,
                                  __nv_bfloat16* __restrict__ outb) {
    int t = blockIdx.x;
    const float* row = in + (size_t)t * CD;
    float ss = 0.f;
    for (int d = threadIdx.x; d < CD; d += 256) { float v = row[d]; ss += v * v; }
    __shared__ float red[256];
    red[threadIdx.x] = ss; __syncthreads();
    for (int st = 128; st > 0; st >>= 1) {
        if (threadIdx.x < st) red[threadIdx.x] += red[threadIdx.x + st];
        __syncthreads();
    }
    float scale = rsqrtf(red[0] / (float)CD + CEPS);
    for (int d = threadIdx.x; d < CD; d += 256) {
        float v = row[d] * scale * w[d];
        out[(size_t)t * CD + d] = v;
        outb[(size_t)t * CD + d] = __float2bfloat16(v);
    }
}

// ---------------- scalar GEMM (router: exact fp32 feeds top-k) -------
__global__ void gemm64(const float* __restrict__ A, const float* __restrict__ Bm,
                       const float* __restrict__ res, float* __restrict__ C,
                       int M, int N, int K) {
    __shared__ float As[16][65];
    __shared__ float Bs[16][64];
    int tid = threadIdx.x;
    int tx = tid & 15, ty = tid >> 4;
    int m0 = blockIdx.y * 64, n0 = blockIdx.x * 64;
    int arow = tid >> 2;
    int acol = (tid & 3) * 4;
    int blin = tid * 4;
    int brow = blin >> 6;
    int bcol = blin & 63;
    const float* Aptr = A + (size_t)(m0 + arow) * K + acol;
    const float* Bptr = Bm + (size_t)brow * N + n0 + bcol;
    float acc[4][4] = {};
    for (int k0 = 0; k0 < K; k0 += 16) {
        float4 av = *(const float4*)(Aptr + k0);
        float4 bv = *(const float4*)(Bptr + (size_t)k0 * N);
        As[acol + 0][arow] = av.x; As[acol + 1][arow] = av.y;
        As[acol + 2][arow] = av.z; As[acol + 3][arow] = av.w;
        *(float4*)&Bs[brow][bcol] = bv;
        __syncthreads();
#pragma unroll
        for (int kk = 0; kk < 16; kk++) {
            float a[4], b[4];
#pragma unroll
            for (int i = 0; i < 4; i++) a[i] = As[kk][ty * 4 + i];
#pragma unroll
            for (int j = 0; j < 4; j++) b[j] = Bs[kk][tx * 4 + j];
#pragma unroll
            for (int i = 0; i < 4; i++)
#pragma unroll
                for (int j = 0; j < 4; j++) acc[i][j] += a[i] * b[j];
        }
        __syncthreads();
    }
#pragma unroll
    for (int i = 0; i < 4; i++)
#pragma unroll
        for (int j = 0; j < 4; j++) {
            size_t idx = (size_t)(m0 + ty * 4 + i) * N + n0 + tx * 4 + j;
            C[idx] = acc[i][j] + (res ? res[idx] : 0.f);
        }
}

// ---------------- fragment types ----------------
using FragAT = wmma::fragment<wmma::matrix_a, 16, 16, 8, wmma::precision::tf32, wmma::row_major>;
using FragBT = wmma::fragment<wmma::matrix_b, 16, 16, 8, wmma::precision::tf32, wmma::row_major>;
using FragAB = wmma::fragment<wmma::matrix_a, 16, 16, 16, __nv_bfloat16, wmma::row_major>;
using FragBB = wmma::fragment<wmma::matrix_b, 16, 16, 16, __nv_bfloat16, wmma::row_major>;
using FragC  = wmma::fragment<wmma::accumulator, 16, 16, 8, float>;
using FragCB = wmma::fragment<wmma::accumulator, 16, 16, 16, float>;

__device__ __forceinline__ void ld_at(FragAT& f, const float* p, int ld) {
    wmma::load_matrix_sync(f, p, ld);
#pragma unroll
    for (int i = 0; i < f.num_elements; i++) f.x[i] = wmma::__float_to_tf32(f.x[i]);
}
__device__ __forceinline__ void ld_bt(FragBT& f, const float* p, int ld) {
    wmma::load_matrix_sync(f, p, ld);
#pragma unroll
    for (int i = 0; i < f.num_elements; i++) f.x[i] = wmma::__float_to_tf32(f.x[i]);
}

// ================= TF32 dense GEMM body (shared by qkv + generic) =======
constexpr int SM_TF32 = 2*128*36*4 + 2*32*68*4;   // 54272

__device__ __forceinline__
void gemm_tf32_body(char* smraw, const float* __restrict__ A, const float* __restrict__ B,
                    const float* __restrict__ res, float* __restrict__ C,
                    int N, int K, int m0, int n0) {
    float (*As)[128][36] = (float(*)[128][36])smraw;
    float (*Bs)[32][68]  = (float(*)[32][68])(smraw + 2*128*36*4);
    int tid = threadIdx.x;
    int w = tid >> 5, wm = w & 3, wn = w >> 2;

    int a_row = tid >> 3, a_c4 = (tid & 7) * 4;
    int b_row = tid >> 4, b_c4 = (tid & 15) * 4;

    FragC acc[2][2];
#pragma unroll
    for (int i = 0; i < 2; i++)
#pragma unroll
        for (int j = 0; j < 2; j++) wmma::fill_fragment(acc[i][j], 0.f);

    float4 ra[4], rb[2];
    int nk = K / 32;
#pragma unroll
    for (int it = 0; it < 4; it++)
        ra[it] = *(const float4*)&A[(size_t)(m0 + a_row + it * 32) * K + a_c4];
#pragma unroll
    for (int it = 0; it < 2; it++)
        rb[it] = *(const float4*)&B[(size_t)(b_row + it * 16) * N + n0 + b_c4];
#pragma unroll
    for (int it = 0; it < 4; it++) *(float4*)&As[0][a_row + it * 32][a_c4] = ra[it];
#pragma unroll
    for (int it = 0; it < 2; it++) *(float4*)&Bs[0][b_row + it * 16][b_c4] = rb[it];
    __syncthreads();

    for (int k = 0; k < nk; k++) {
        int cur = k & 1;
        if (k + 1 < nk) {
            int k0 = (k + 1) * 32;
#pragma unroll
            for (int it = 0; it < 4; it++)
                ra[it] = *(const float4*)&A[(size_t)(m0 + a_row + it * 32) * K + k0 + a_c4];
#pragma unroll
            for (int it = 0; it < 2; it++)
                rb[it] = *(const float4*)&B[(size_t)(k0 + b_row + it * 16) * N + n0 + b_c4];
        }
#pragma unroll
        for (int kk = 0; kk < 4; kk++) {
            FragAT a[2]; FragBT b[2];
#pragma unroll
            for (int i = 0; i < 2; i++) ld_at(a[i], &As[cur][wm * 32 + i * 16][kk * 8], 36);
#pragma unroll
            for (int j = 0; j < 2; j++) ld_bt(b[j], &Bs[cur][kk * 8][wn * 32 + j * 16], 68);
#pragma unroll
            for (int i = 0; i < 2; i++)
#pragma unroll
                for (int j = 0; j < 2; j++) wmma::mma_sync(acc[i][j], a[i], b[j], acc[i][j]);
        }
        if (k + 1 < nk) {
            int nxt = cur ^ 1;
#pragma unroll
            for (int it = 0; it < 4; it++) *(float4*)&As[nxt][a_row + it * 32][a_c4] = ra[it];
#pragma unroll
            for (int it = 0; it < 2; it++) *(float4*)&Bs[nxt][b_row + it * 16][b_c4] = rb[it];
        }
        __syncthreads();
    }
#pragma unroll
    for (int i = 0; i < 2; i++)
#pragma unroll
        for (int j = 0; j < 2; j++) {
            size_t co = (size_t)(m0 + wm * 32 + i * 16) * N + n0 + wn * 32 + j * 16;
            if (res) {
                FragC r;
                wmma::load_matrix_sync(r, res + co, N, wmma::mem_row_major);
#pragma unroll
                for (int e2 = 0; e2 < r.num_elements; e2++) acc[i][j].x[e2] += r.x[e2];
            }
            wmma::store_matrix_sync(C + co, acc[i][j], N, wmma::mem_row_major);
        }
}

__global__ __launch_bounds__(256, 2)
void gemm_tf32_pipe(const float* __restrict__ A, const float* __restrict__ B,
                    const float* __restrict__ res, float* __restrict__ C,
                    int N, int K) {
    extern __shared__ char smraw[];
    gemm_tf32_body(smraw, A, B, res, C, N, K, blockIdx.y * 128, blockIdx.x * 64);
}

// fused QKV projection: one launch, 48 n-tiles (32 Q + 8 K + 8 V)
__global__ __launch_bounds__(256, 2)
void qkv_tf32(const float* __restrict__ A,
              const float* __restrict__ wq, const float* __restrict__ wk,
              const float* __restrict__ wv) {
    extern __shared__ char smraw[];
    int nt = blockIdx.x;
    const float* B; float* C; int N, n0;
    if (nt < 32)      { B = wq; C = g_q; N = CH  * CHD; n0 = nt * 64; }
    else if (nt < 40) { B = wk; C = g_k; N = CKVH* CHD; n0 = (nt - 32) * 64; }
    else              { B = wv; C = g_v; N = CKVH* CHD; n0 = (nt - 40) * 64; }
    gemm_tf32_body(smraw, A, B, nullptr, C, N, CD, blockIdx.y * 128, n0);
}

// ---------------- per-head q/k rmsnorm + rope ----------------
__global__ void qknorm_rope_kernel(const float* __restrict__ cos_,
                                   const float* __restrict__ sin_,
                                   const float* __restrict__ qn_w,
                                   const float* __restrict__ kn_w) {
    int t = blockIdx.x;
    int hy = blockIdx.y;
    int d = threadIdx.x;
    float* ptr; const float* w;
    if (hy < CH) { ptr = g_q + ((size_t)t * CH + hy) * CHD;          w = qn_w; }
    else         { ptr = g_k + ((size_t)t * CKVH + (hy - CH)) * CHD; w = kn_w; }
    float v = ptr[d];
    float ss = v * v;
#pragma unroll
    for (int off = 16; off > 0; off >>= 1) ss += __shfl_xor_sync(0xffffffffu, ss, off);
    __shared__ float ws[4];
    if ((d & 31) == 0) ws[d >> 5] = ss;
    __syncthreads();
    float tot = ws[0] + ws[1] + ws[2] + ws[3];
    float nrm = v * rsqrtf(tot / (float)CHD + CEPS) * w[d];
    __shared__ float nbuf[128];
    nbuf[d] = nrm;
    __syncthreads();
    float rot = (d < 64) ? -nbuf[d + 64] : nbuf[d - 64];
    float c = cos_[(size_t)t * CHD + d];
    float s = sin_[(size_t)t * CHD + d];
    ptr[d] = nrm * c + rot * s;
}

// ---------------- flash attention v2: float4 LDS + dedup softmax ----------
__global__ void attn_kernel() {
    int qt = blockIdx.x;
    int h  = blockIdx.y;
    int b  = blockIdx.z;
    int kvh = h / (CH / CKVH);
    int tid = threadIdx.x;
    int r  = tid >> 2;          // 0..31
    int qd = tid & 3;           // 0..3
    __shared__ float Qs[32][132];
    __shared__ float KVs[32][132];
    __shared__ float Ss[32][33];

    for (int i = tid; i < 32 * 128; i += 128) {
        int rr = i >> 7, dd = i & 127;
        Qs[rr][dd] = g_q[((size_t)(b * CS + qt * 32 + rr) * CH + h) * CHD + dd];
    }
    float acc[32];
#pragma unroll
    for (int i = 0; i < 32; i++) acc[i] = 0.f;
    float m = -1e30f, l = 0.f;
    const float scale = 0.088388347648318447f;   // 1/sqrt(128)
    int qg = qt * 32 + r;

    for (int jt = 0; jt <= qt; jt++) {
        __syncthreads();
        for (int i = tid; i < 32 * 128; i += 128) {
            int rr = i >> 7, dd = i & 127;
            KVs[rr][dd] = g_k[((size_t)(b * CS + jt * 32 + rr) * CKVH + kvh) * CHD + dd];
        }
        __syncthreads();
        float sc[8];
#pragma unroll
        for (int jj = 0; jj < 8; jj++) sc[jj] = 0.f;
        const float4* q4 = (const float4*)&Qs[r][0];
        for (int d4 = 0; d4 < 32; d4++) {
            float4 qv = q4[d4];
#pragma unroll
            for (int jj = 0; jj < 8; jj++) {
                float4 kv = *(const float4*)&KVs[qd + 4 * jj][d4 * 4];
                sc[jj] += qv.x * kv.x + qv.y * kv.y + qv.z * kv.z + qv.w * kv.w;
            }
        }
        float lm = -1e30f;
        float p[8];
#pragma unroll
        for (int jj = 0; jj < 8; jj++) {
            int kg = jt * 32 + qd + 4 * jj;
            float v = sc[jj] * scale;
            if (kg > qg) v = -1e30f;
            p[jj] = v;
            lm = fmaxf(lm, v);
        }
        lm = fmaxf(lm, __shfl_xor_sync(0xffffffffu, lm, 1));
        lm = fmaxf(lm, __shfl_xor_sync(0xffffffffu, lm, 2));
        float tm = fmaxf(m, lm);
        float alpha = expf(m - tm);
        float lsum = 0.f;
#pragma unroll
        for (int jj = 0; jj < 8; jj++) { p[jj] = expf(p[jj] - tm); lsum += p[jj]; }
        lsum += __shfl_xor_sync(0xffffffffu, lsum, 1);
        lsum += __shfl_xor_sync(0xffffffffu, lsum, 2);
        l = l * alpha + lsum;
        m = tm;
#pragma unroll
        for (int jj = 0; jj < 8; jj++) Ss[r][qd + 4 * jj] = p[jj];
        __syncthreads();
        for (int i = tid; i < 32 * 128; i += 128) {
            int rr = i >> 7, dd = i & 127;
            KVs[rr][dd] = g_v[((size_t)(b * CS + jt * 32 + rr) * CKVH + kvh) * CHD + dd];
        }
        __syncthreads();
#pragma unroll
        for (int dd = 0; dd < 32; dd++) acc[dd] *= alpha;
        for (int c = 0; c < 32; c++) {
            float pv = Ss[r][c];
#pragma unroll
            for (int d4 = 0; d4 < 8; d4++) {
                int dd = ((d4 + 2 * qd) & 7) * 4;
                float4 kv = *(const float4*)&KVs[c][qd * 32 + dd];
                acc[dd + 0] += pv * kv.x;
                acc[dd + 1] += pv * kv.y;
                acc[dd + 2] += pv * kv.z;
                acc[dd + 3] += pv * kv.w;
            }
        }
    }
    float inv = 1.f / l;
    int t = b * CS + qt * 32 + r;
    float* op = &g_o[((size_t)t * CH + h) * CHD + qd * 32];
#pragma unroll
    for (int d4 = 0; d4 < 8; d4++) {
        float4 v;
        v.x = acc[d4 * 4 + 0] * inv;
        v.y = acc[d4 * 4 + 1] * inv;
        v.z = acc[d4 * 4 + 2] * inv;
        v.w = acc[d4 * 4 + 3] * inv;
        *(float4*)&op[d4 * 4] = v;
    }
}

// ---------------- router softmax + top-8 ----------------
__global__ void topk_kernel() {
    int t = blockIdx.x, e = threadIdx.x;
    __shared__ float red[64];
    __shared__ int   redi[64];
    __shared__ float tv[8];
    __shared__ int   ti[8];
    float lg = g_logits[t * CE + e];
    red[e] = lg; __syncthreads();
    for (int st = 32; st > 0; st >>= 1) {
        if (e < st) red[e] = fmaxf(red[e], red[e + st]);
        __syncthreads();
    }
    float mx = red[0]; __syncthreads();
    float ex = expf(lg - mx);
    red[e] = ex; __syncthreads();
    for (int st = 32; st > 0; st >>= 1) {
        if (e < st) red[e] += red[e + st];
        __syncthreads();
    }
    float sum = red[0]; __syncthreads();
    float sel = ex / sum;
    for (int k = 0; k < 8; k++) {
        red[e] = sel; redi[e] = e; __syncthreads();
        for (int st = 32; st > 0; st >>= 1) {
            if (e < st) {
                if (red[e + st] > red[e]) { red[e] = red[e + st]; redi[e] = redi[e + st]; }
            }
            __syncthreads();
        }
        if (e == 0) { tv[k] = red[0]; ti[k] = redi[0]; }
        __syncthreads();
        if (e == ti[k]) sel = -1.f;
        __syncthreads();
    }
    if (e < 8) {
        float s8 = 0.f;
#pragma unroll
        for (int k = 0; k < 8; k++) s8 += tv[k];
        g_topi[t * CK + e] = ti[e];
        g_topw[t * CK + e] = tv[e] / s8;
    }
}

// ---------------- routing bookkeeping ----------------
__global__ void zero_counts_kernel() { if (threadIdx.x < CE) g_counts[threadIdx.x] = 0; }

__global__ void count_kernel() {
    int i = blockIdx.x * blockDim.x + threadIdx.x;
    if (i < NSLOT) atomicAdd(&g_counts[g_topi[i]], 1);
}

__global__ void scan_kernel() {
    int acc = 0;
    for (int e = 0; e < CE; e++) {
        g_offsets[e] = acc;
        g_cursor[e]  = acc;
        acc += ((g_counts[e] + 127) >> 7) << 7;
    }
}

__global__ void init_slots_kernel() {
    int i = blockIdx.x * blockDim.x + threadIdx.x;
    if (i < PADTOT) g_slot_token[i] = 0;
}

__global__ void fill_kernel() {
    int i = blockIdx.x * blockDim.x + threadIdx.x;
    if (i < NSLOT) {
        int e = g_topi[i];
        int p = atomicAdd(&g_cursor[e], 1);
        g_slot_token[p] = i >> 3;
        g_pos_of[i] = p;
    }
}

// ================= unified MoE bf16 GEMM, BK=32 (2 CTAs/SM; R4-proven) =====
// MODE 0: gate = ht_bf(gather) @ w_gate -> g_gate (fp32)
// MODE 1: up   = ht_bf(gather) @ w_up; epilogue act_bf = silu(g_gate)*u
// MODE 2: down = act_bf @ w_down -> g_y (fp32)
// smem: As bf16[2][128][40] @0 (20480) | Bs bf16[2][32][72] @20480 (9216)
//       stok int[128] @29696 (512) | scr f32[8][16][16] @30208 (8192) = 38400
constexpr int SM_MOE = 38400;

template<int MODE>
__global__ __launch_bounds__(256, 2)
void moe_gemm_bf16(const float* __restrict__ W) {
    extern __shared__ char smraw[];
    __nv_bfloat16 (*As)[128][40] = (__nv_bfloat16(*)[128][40])smraw;
    __nv_bfloat16 (*Bs)[32][72]  = (__nv_bfloat16(*)[32][72])(smraw + 20480);
    int* stok = (int*)(smraw + 29696);
    float (*scr)[16][16] = (float(*)[16][16])(smraw + 30208);

    constexpr int KDIM = (MODE == 2) ? CF : CD;
    constexpr int NDIM = (MODE == 2) ? CD : CF;

    int e = blockIdx.y;
    int n0 = blockIdx.x * 64;
    int off = g_offsets[e], cnt = g_counts[e];
    int ntiles = (cnt + 127) >> 7;
    const float* Bm = W + (size_t)e * KDIM * NDIM;

    int tid = threadIdx.x;
    int w = tid >> 5, wm = w & 3, wn = w >> 2;
    int lane = tid & 31;
    int b_row = tid >> 4, b_c4 = (tid & 15) * 4;

    for (int rt = 0; rt < ntiles; rt++) {
        size_t abase = (size_t)(off + rt * 128);
        if (MODE < 2) {
            if (tid < 128) stok[tid] = g_slot_token[abase + tid];
            __syncthreads();
        }

        FragCB acc[2][2];
#pragma unroll
        for (int i = 0; i < 2; i++)
#pragma unroll
            for (int j = 0; j < 2; j++) wmma::fill_fragment(acc[i][j], 0.f);

        uint4 raA[2]; float4 rb[2];
        constexpr int nk = KDIM / 32;
        // prologue
#pragma unroll
        for (int it = 0; it < 2; it++) {
            int i = tid + it * 256;
            int row = i >> 2, c8 = (i & 3) * 8;
            if (MODE < 2)
                raA[it] = *(const uint4*)&g_ht_bf[(size_t)stok[row] * CD + c8];
            else
                raA[it] = *(const uint4*)&g_act_bf[(abase + row) * CF + c8];
        }
#pragma unroll
        for (int it = 0; it < 2; it++)
            rb[it] = *(const float4*)&Bm[(size_t)(b_row + it * 16) * NDIM + n0 + b_c4];
#pragma unroll
        for (int it = 0; it < 2; it++) {
            int i = tid + it * 256;
            int row = i >> 2, c8 = (i & 3) * 8;
            *(uint4*)&As[0][row][c8] = raA[it];
        }
#pragma unroll
        for (int it = 0; it < 2; it++)
            st_bf4(&Bs[0][b_row + it * 16][b_c4], rb[it]);
        __syncthreads();

        for (int k = 0; k < nk; k++) {
            int cur = k & 1;
            if (k + 1 < nk) {
                int k0 = (k + 1) * 32;
#pragma unroll
                for (int it = 0; it < 2; it++) {
                    int i = tid + it * 256;
                    int row = i >> 2, c8 = (i & 3) * 8;
                    if (MODE < 2)
                        raA[it] = *(const uint4*)&g_ht_bf[(size_t)stok[row] * CD + k0 + c8];
                    else
                        raA[it] = *(const uint4*)&g_act_bf[(abase + row) * CF + k0 + c8];
                }
#pragma unroll
                for (int it = 0; it < 2; it++)
                    rb[it] = *(const float4*)&Bm[(size_t)(k0 + b_row + it * 16) * NDIM + n0 + b_c4];
            }
#pragma unroll
            for (int kk = 0; kk < 2; kk++) {
                FragAB a[2]; FragBB b[2];
#pragma unroll
                for (int i = 0; i < 2; i++)
                    wmma::load_matrix_sync(a[i], &As[cur][wm * 32 + i * 16][kk * 16], 40);
#pragma unroll
                for (int j = 0; j < 2; j++)
                    wmma::load_matrix_sync(b[j], &Bs[cur][kk * 16][wn * 32 + j * 16], 72);
#pragma unroll
                for (int i = 0; i < 2; i++)
#pragma unroll
                    for (int j = 0; j < 2; j++) wmma::mma_sync(acc[i][j], a[i], b[j], acc[i][j]);
            }
            if (k + 1 < nk) {
                int nxt = cur ^ 1;
#pragma unroll
                for (int it = 0; it < 2; it++) {
                    int i = tid + it * 256;
                    int row = i >> 2, c8 = (i & 3) * 8;
                    *(uint4*)&As[nxt][row][c8] = raA[it];
                }
#pragma unroll
                for (int it = 0; it < 2; it++)
                    st_bf4(&Bs[nxt][b_row + it * 16][b_c4], rb[it]);
            }
            __syncthreads();
        }

        // epilogue
        if (MODE == 0) {
#pragma unroll
            for (int i = 0; i < 2; i++)
#pragma unroll
                for (int j = 0; j < 2; j++) {
                    float* cp = g_gate + (abase + wm * 32 + i * 16) * CF + n0 + wn * 32 + j * 16;
                    wmma::store_matrix_sync(cp, acc[i][j], CF, wmma::mem_row_major);
                }
        } else if (MODE == 2) {
#pragma unroll
            for (int i = 0; i < 2; i++)
#pragma unroll
                for (int j = 0; j < 2; j++) {
                    float* cp = g_y + (abase + wm * 32 + i * 16) * CD + n0 + wn * 32 + j * 16;
                    wmma::store_matrix_sync(cp, acc[i][j], CD, wmma::mem_row_major);
                }
        } else {
#pragma unroll
            for (int i = 0; i < 2; i++)
#pragma unroll
                for (int j = 0; j < 2; j++) {
                    wmma::store_matrix_sync(&scr[w][0][0], acc[i][j], 16, wmma::mem_row_major);
                    __syncwarp();
                    {
                        int r = lane >> 1, cb = (lane & 1) * 8;
                        size_t grow = abase + wm * 32 + i * 16 + r;
                        int col = n0 + wn * 32 + j * 16 + cb;
                        const float* gp = &g_gate[grow * CF + col];
                        float4 g0 = *(const float4*)gp;
                        float4 g1 = *(const float4*)(gp + 4);
                        float4 u0 = *(float4*)&scr[w][r][cb];
                        float4 u1 = *(float4*)&scr[w][r][cb + 4];
                        float4 o0, o1;
                        o0.x = (g0.x / (1.f + expf(-g0.x))) * u0.x;
                        o0.y = (g0.y / (1.f + expf(-g0.y))) * u0.y;
                        o0.z = (g0.z / (1.f + expf(-g0.z))) * u0.z;
                        o0.w = (g0.w / (1.f + expf(-g0.w))) * u0.w;
                        o1.x = (g1.x / (1.f + expf(-g1.x))) * u1.x;
                        o1.y = (g1.y / (1.f + expf(-g1.y))) * u1.y;
                        o1.z = (g1.z / (1.f + expf(-g1.z))) * u1.z;
                        o1.w = (g1.w / (1.f + expf(-g1.w))) * u1.w;
                        __nv_bfloat16* dst = g_act_bf + grow * CF + col;
                        st_bf4(dst, o0);
                        st_bf4(dst + 4, o1);
                    }
                    __syncwarp();
                }
        }
        __syncthreads();
    }
}

// ---------------- final combine ----------------
__global__ void final_add_kernel(float* __restrict__ out) {
    int t = blockIdx.x;
    __shared__ int   pos[8];
    __shared__ float w[8];
    if (threadIdx.x < 8) {
        pos[threadIdx.x] = g_pos_of[t * CK + threadIdx.x];
        w[threadIdx.x]   = g_topw[t * CK + threadIdx.x];
    }
    __syncthreads();
    for (int d = threadIdx.x; d < CD; d += 256) {
        float acc = out[(size_t)t * CD + d];
#pragma unroll
        for (int k = 0; k < 8; k++)
            acc += w[k] * g_y[(size_t)pos[k] * CD + d];
        out[(size_t)t * CD + d] = acc;
    }
}

// ---------------- launch ----------------
extern "C" void kernel_launch(void* const* d_in, const int* in_sizes, int n_in,
                              void* d_out, int out_size) {
    const float* x        = (const float*)d_in[0];
    const float* cos_     = (const float*)d_in[1];
    const float* sin_     = (const float*)d_in[2];
    const float* ln1_w    = (const float*)d_in[3];
    const float* wq       = (const float*)d_in[4];
    const float* wk       = (const float*)d_in[5];
    const float* wv       = (const float*)d_in[6];
    const float* wo       = (const float*)d_in[7];
    const float* qn_w     = (const float*)d_in[8];
    const float* kn_w     = (const float*)d_in[9];
    const float* ln2_w    = (const float*)d_in[10];
    const float* router_w = (const float*)d_in[11];
    const float* w_gate   = (const float*)d_in[12];
    const float* w_up     = (const float*)d_in[13];
    const float* w_down   = (const float*)d_in[14];
    float* out = (float*)d_out;

    cudaFuncSetAttribute(gemm_tf32_pipe,   cudaFuncAttributeMaxDynamicSharedMemorySize, SM_TF32);
    cudaFuncSetAttribute(qkv_tf32,         cudaFuncAttributeMaxDynamicSharedMemorySize, SM_TF32);
    cudaFuncSetAttribute(moe_gemm_bf16<0>, cudaFuncAttributeMaxDynamicSharedMemorySize, SM_MOE);
    cudaFuncSetAttribute(moe_gemm_bf16<1>, cudaFuncAttributeMaxDynamicSharedMemorySize, SM_MOE);
    cudaFuncSetAttribute(moe_gemm_bf16<2>, cudaFuncAttributeMaxDynamicSharedMemorySize, SM_MOE);

    float *p_h, *p_o, *p_ht, *p_logits;
    __nv_bfloat16 *p_ht_bf;
    cudaGetSymbolAddress((void**)&p_h,  g_h);
    cudaGetSymbolAddress((void**)&p_o,  g_o);
    cudaGetSymbolAddress((void**)&p_ht, g_ht);
    cudaGetSymbolAddress((void**)&p_ht_bf, g_ht_bf);
    cudaGetSymbolAddress((void**)&p_logits, g_logits);

    // 1. h = rmsnorm(x)
    rmsnorm_kernel<<<CT, 256>>>(x, ln1_w, p_h);
    // 2. fused q,k,v projections (one launch, 768 blocks)
    qkv_tf32<<<dim3(48, CT / 128), 256, SM_TF32>>>(p_h, wq, wk, wv);
    // 3. per-head q/k rmsnorm + rope
    qknorm_rope_kernel<<<dim3(CT, CH + CKVH), 128>>>(cos_, sin_, qn_w, kn_w);
    // 4. attention (exact fp32, vectorized + dedup softmax)
    attn_kernel<<<dim3(CS / 32, CH, CB), 128>>>();
    // 5. out = o @ wo + x
    gemm_tf32_pipe<<<dim3(CD / 64, CT / 128), 256, SM_TF32>>>(p_o, wo, x, out, CD, CD);
    // 6. ht = rmsnorm(out), fp32 + bf16
    rmsnorm_bf_kernel<<<CT, 256>>>(out, ln2_w, p_ht, p_ht_bf);
    // 7. router logits (exact fp32) + top-8
    gemm64<<<dim3(CE / 64, CT / 64), 256>>>(p_ht, router_w, nullptr, p_logits, CT, CE, CD);
    topk_kernel<<<CT, 64>>>();
    // 8. routing bookkeeping
    zero_counts_kernel<<<1, 64>>>();
    count_kernel<<<NSLOT / 256, 256>>>();
    scan_kernel<<<1, 1>>>();
    init_slots_kernel<<<PADTOT / 256, 256>>>();
    fill_kernel<<<NSLOT / 256, 256>>>();
    // 9. MoE: gate, up(+silu), down (bf16 BK=32, 2 CTAs/SM — R4-proven)
    moe_gemm_bf16<0><<<dim3(CF / 64, CE), 256, SM_MOE>>>(w_gate);
    moe_gemm_bf16<1><<<dim3(CF / 64, CE), 256, SM_MOE>>>(w_up);
    moe_gemm_bf16<2><<<dim3(CD / 64, CE), 256, SM_MOE>>>(w_down);
    // 10. deterministic per-token combine
    final_add_kernel<<<CT, 256>>>(out);
}

// round 7
// speedup vs baseline: 2.7308x; 2.7308x over previous
#include <cuda_runtime.h>
#include <cuda_bf16.h>
#include <math.h>
#include <mma.h>
using namespace nvcuda;

// ---------------- problem constants ----------------
constexpr int CB  = 2;
constexpr int CS  = 1024;
constexpr int CD  = 2048;
constexpr int CH  = 16;
constexpr int CKVH= 4;
constexpr int CHD = 128;
constexpr int CE  = 64;
constexpr int CK  = 8;
constexpr int CF  = 768;
constexpr int CT  = CB * CS;             // 2048
constexpr float CEPS = 1e-6f;
constexpr int NSLOT = CT * CK;           // 16384
constexpr int PADTOT = NSLOT + CE * 128; // 24576

// ---------------- scratch ----------------
__device__ float g_h   [CT * CD];
__device__ float g_q   [CT * CH  * CHD];
__device__ float g_k   [CT * CKVH* CHD];
__device__ float g_v   [CT * CKVH* CHD];
__device__ float g_o   [CT * CH  * CHD];
__device__ float g_ht  [CT * CD];
__device__ __nv_bfloat16 g_ht_bf[CT * CD];
__device__ float g_logits[CT * CE];
__device__ int   g_topi[CT * CK];
__device__ float g_topw[CT * CK];
__device__ int   g_counts[CE];
__device__ int   g_offsets[CE];
__device__ int   g_cursor[CE];
__device__ int   g_slot_token[PADTOT];
__device__ int   g_pos_of[NSLOT];
__device__ float g_gate[(size_t)PADTOT * CF];
__device__ __nv_bfloat16 g_act_bf[(size_t)PADTOT * CF];
__device__ float g_y   [(size_t)PADTOT * CD];

// ---------------- helpers ----------------
__device__ __forceinline__ void st_bf4(__nv_bfloat16* p, float4 v) {
    __nv_bfloat162 lo = __floats2bfloat162_rn(v.x, v.y);
    __nv_bfloat162 hi = __floats2bfloat162_rn(v.z, v.w);
    uint2 u;
    u.x = *(unsigned int*)&lo;
    u.y = *(unsigned int*)&hi;
    *(uint2*)p = u;
}

// ---------------- rmsnorm ----------------
__global__ void rmsnorm_kernel(const float* __restrict__ in,
                               const float* __restrict__ w,
                               float* __restrict__ out) {
    int t = blockIdx.x;
    const float* row = in + (size_t)t * CD;
    float ss = 0.f;
    for (int d = threadIdx.x; d < CD; d += 256) { float v = row[d]; ss += v * v; }
    __shared__ float red[256];
    red[threadIdx.x] = ss; __syncthreads();
    for (int st = 128; st > 0; st >>= 1) {
        if (threadIdx.x < st) red[threadIdx.x] += red[threadIdx.x + st];
        __syncthreads();
    }
    float scale = rsqrtf(red[0] / (float)CD + CEPS);
    for (int d = threadIdx.x; d < CD; d += 256)
        out[(size_t)t * CD + d] = row[d] * scale * w[d];
}

__global__ void rmsnorm_bf_kernel(const float* __restrict__ in,
                                  const float* __restrict__ w,
                                  float* __restrict__ out,
                                  __nv_bfloat16* __restrict__ outb) {
    int t = blockIdx.x;
    const float* row = in + (size_t)t * CD;
    float ss = 0.f;
    for (int d = threadIdx.x; d < CD; d += 256) { float v = row[d]; ss += v * v; }
    __shared__ float red[256];
    red[threadIdx.x] = ss; __syncthreads();
    for (int st = 128; st > 0; st >>= 1) {
        if (threadIdx.x < st) red[threadIdx.x] += red[threadIdx.x + st];
        __syncthreads();
    }
    float scale = rsqrtf(red[0] / (float)CD + CEPS);
    for (int d = threadIdx.x; d < CD; d += 256) {
        float v = row[d] * scale * w[d];
        out[(size_t)t * CD + d] = v;
        outb[(size_t)t * CD + d] = __float2bfloat16(v);
    }
}

// ---------------- scalar GEMM (router: exact fp32 feeds top-k) -------
__global__ void gemm64(const float* __restrict__ A, const float* __restrict__ Bm,
                       const float* __restrict__ res, float* __restrict__ C,
                       int M, int N, int K) {
    __shared__ float As[16][65];
    __shared__ float Bs[16][64];
    int tid = threadIdx.x;
    int tx = tid & 15, ty = tid >> 4;
    int m0 = blockIdx.y * 64, n0 = blockIdx.x * 64;
    int arow = tid >> 2;
    int acol = (tid & 3) * 4;
    int blin = tid * 4;
    int brow = blin >> 6;
    int bcol = blin & 63;
    const float* Aptr = A + (size_t)(m0 + arow) * K + acol;
    const float* Bptr = Bm + (size_t)brow * N + n0 + bcol;
    float acc[4][4] = {};
    for (int k0 = 0; k0 < K; k0 += 16) {
        float4 av = *(const float4*)(Aptr + k0);
        float4 bv = *(const float4*)(Bptr + (size_t)k0 * N);
        As[acol + 0][arow] = av.x; As[acol + 1][arow] = av.y;
        As[acol + 2][arow] = av.z; As[acol + 3][arow] = av.w;
        *(float4*)&Bs[brow][bcol] = bv;
        __syncthreads();
#pragma unroll
        for (int kk = 0; kk < 16; kk++) {
            float a[4], b[4];
#pragma unroll
            for (int i = 0; i < 4; i++) a[i] = As[kk][ty * 4 + i];
#pragma unroll
            for (int j = 0; j < 4; j++) b[j] = Bs[kk][tx * 4 + j];
#pragma unroll
            for (int i = 0; i < 4; i++)
#pragma unroll
                for (int j = 0; j < 4; j++) acc[i][j] += a[i] * b[j];
        }
        __syncthreads();
    }
#pragma unroll
    for (int i = 0; i < 4; i++)
#pragma unroll
        for (int j = 0; j < 4; j++) {
            size_t idx = (size_t)(m0 + ty * 4 + i) * N + n0 + tx * 4 + j;
            C[idx] = acc[i][j] + (res ? res[idx] : 0.f);
        }
}

// ---------------- fragment types ----------------
using FragAT = wmma::fragment<wmma::matrix_a, 16, 16, 8, wmma::precision::tf32, wmma::row_major>;
using FragBT = wmma::fragment<wmma::matrix_b, 16, 16, 8, wmma::precision::tf32, wmma::row_major>;
using FragAB = wmma::fragment<wmma::matrix_a, 16, 16, 16, __nv_bfloat16, wmma::row_major>;
using FragBB = wmma::fragment<wmma::matrix_b, 16, 16, 16, __nv_bfloat16, wmma::row_major>;
using FragC  = wmma::fragment<wmma::accumulator, 16, 16, 8, float>;
using FragCB = wmma::fragment<wmma::accumulator, 16, 16, 16, float>;

__device__ __forceinline__ void ld_at(FragAT& f, const float* p, int ld) {
    wmma::load_matrix_sync(f, p, ld);
#pragma unroll
    for (int i = 0; i < f.num_elements; i++) f.x[i] = wmma::__float_to_tf32(f.x[i]);
}
__device__ __forceinline__ void ld_bt(FragBT& f, const float* p, int ld) {
    wmma::load_matrix_sync(f, p, ld);
#pragma unroll
    for (int i = 0; i < f.num_elements; i++) f.x[i] = wmma::__float_to_tf32(f.x[i]);
}

// ================= TF32 dense GEMM body (shared by qkv + generic) =======
constexpr int SM_TF32 = 2*128*36*4 + 2*32*68*4;   // 54272

__device__ __forceinline__
void gemm_tf32_body(char* smraw, const float* __restrict__ A, const float* __restrict__ B,
                    const float* __restrict__ res, float* __restrict__ C,
                    int N, int K, int m0, int n0) {
    float (*As)[128][36] = (float(*)[128][36])smraw;
    float (*Bs)[32][68]  = (float(*)[32][68])(smraw + 2*128*36*4);
    int tid = threadIdx.x;
    int w = tid >> 5, wm = w & 3, wn = w >> 2;

    int a_row = tid >> 3, a_c4 = (tid & 7) * 4;
    int b_row = tid >> 4, b_c4 = (tid & 15) * 4;

    FragC acc[2][2];
#pragma unroll
    for (int i = 0; i < 2; i++)
#pragma unroll
        for (int j = 0; j < 2; j++) wmma::fill_fragment(acc[i][j], 0.f);

    float4 ra[4], rb[2];
    int nk = K / 32;
#pragma unroll
    for (int it = 0; it < 4; it++)
        ra[it] = *(const float4*)&A[(size_t)(m0 + a_row + it * 32) * K + a_c4];
#pragma unroll
    for (int it = 0; it < 2; it++)
        rb[it] = *(const float4*)&B[(size_t)(b_row + it * 16) * N + n0 + b_c4];
#pragma unroll
    for (int it = 0; it < 4; it++) *(float4*)&As[0][a_row + it * 32][a_c4] = ra[it];
#pragma unroll
    for (int it = 0; it < 2; it++) *(float4*)&Bs[0][b_row + it * 16][b_c4] = rb[it];
    __syncthreads();

    for (int k = 0; k < nk; k++) {
        int cur = k & 1;
        if (k + 1 < nk) {
            int k0 = (k + 1) * 32;
#pragma unroll
            for (int it = 0; it < 4; it++)
                ra[it] = *(const float4*)&A[(size_t)(m0 + a_row + it * 32) * K + k0 + a_c4];
#pragma unroll
            for (int it = 0; it < 2; it++)
                rb[it] = *(const float4*)&B[(size_t)(k0 + b_row + it * 16) * N + n0 + b_c4];
        }
#pragma unroll
        for (int kk = 0; kk < 4; kk++) {
            FragAT a[2]; FragBT b[2];
#pragma unroll
            for (int i = 0; i < 2; i++) ld_at(a[i], &As[cur][wm * 32 + i * 16][kk * 8], 36);
#pragma unroll
            for (int j = 0; j < 2; j++) ld_bt(b[j], &Bs[cur][kk * 8][wn * 32 + j * 16], 68);
#pragma unroll
            for (int i = 0; i < 2; i++)
#pragma unroll
                for (int j = 0; j < 2; j++) wmma::mma_sync(acc[i][j], a[i], b[j], acc[i][j]);
        }
        if (k + 1 < nk) {
            int nxt = cur ^ 1;
#pragma unroll
            for (int it = 0; it < 4; it++) *(float4*)&As[nxt][a_row + it * 32][a_c4] = ra[it];
#pragma unroll
            for (int it = 0; it < 2; it++) *(float4*)&Bs[nxt][b_row + it * 16][b_c4] = rb[it];
        }
        __syncthreads();
    }
#pragma unroll
    for (int i = 0; i < 2; i++)
#pragma unroll
        for (int j = 0; j < 2; j++) {
            size_t co = (size_t)(m0 + wm * 32 + i * 16) * N + n0 + wn * 32 + j * 16;
            if (res) {
                FragC r;
                wmma::load_matrix_sync(r, res + co, N, wmma::mem_row_major);
#pragma unroll
                for (int e2 = 0; e2 < r.num_elements; e2++) acc[i][j].x[e2] += r.x[e2];
            }
            wmma::store_matrix_sync(C + co, acc[i][j], N, wmma::mem_row_major);
        }
}

__global__ __launch_bounds__(256, 2)
void gemm_tf32_pipe(const float* __restrict__ A, const float* __restrict__ B,
                    const float* __restrict__ res, float* __restrict__ C,
                    int N, int K) {
    extern __shared__ char smraw[];
    gemm_tf32_body(smraw, A, B, res, C, N, K, blockIdx.y * 128, blockIdx.x * 64);
}

// fused QKV projection: one launch, 48 n-tiles (32 Q + 8 K + 8 V)
__global__ __launch_bounds__(256, 2)
void qkv_tf32(const float* __restrict__ A,
              const float* __restrict__ wq, const float* __restrict__ wk,
              const float* __restrict__ wv) {
    extern __shared__ char smraw[];
    int nt = blockIdx.x;
    const float* B; float* C; int N, n0;
    if (nt < 32)      { B = wq; C = g_q; N = CH  * CHD; n0 = nt * 64; }
    else if (nt < 40) { B = wk; C = g_k; N = CKVH* CHD; n0 = (nt - 32) * 64; }
    else              { B = wv; C = g_v; N = CKVH* CHD; n0 = (nt - 40) * 64; }
    gemm_tf32_body(smraw, A, B, nullptr, C, N, CD, blockIdx.y * 128, n0);
}

// ---------------- per-head q/k rmsnorm + rope ----------------
__global__ void qknorm_rope_kernel(const float* __restrict__ cos_,
                                   const float* __restrict__ sin_,
                                   const float* __restrict__ qn_w,
                                   const float* __restrict__ kn_w) {
    int t = blockIdx.x;
    int hy = blockIdx.y;
    int d = threadIdx.x;
    float* ptr; const float* w;
    if (hy < CH) { ptr = g_q + ((size_t)t * CH + hy) * CHD;          w = qn_w; }
    else         { ptr = g_k + ((size_t)t * CKVH + (hy - CH)) * CHD; w = kn_w; }
    float v = ptr[d];
    float ss = v * v;
#pragma unroll
    for (int off = 16; off > 0; off >>= 1) ss += __shfl_xor_sync(0xffffffffu, ss, off);
    __shared__ float ws[4];
    if ((d & 31) == 0) ws[d >> 5] = ss;
    __syncthreads();
    float tot = ws[0] + ws[1] + ws[2] + ws[3];
    float nrm = v * rsqrtf(tot / (float)CHD + CEPS) * w[d];
    __shared__ float nbuf[128];
    nbuf[d] = nrm;
    __syncthreads();
    float rot = (d < 64) ? -nbuf[d + 64] : nbuf[d - 64];
    float c = cos_[(size_t)t * CHD + d];
    float s = sin_[(size_t)t * CHD + d];
    ptr[d] = nrm * c + rot * s;
}

// ---------------- flash attention v2.1 ----------------
// 128 threads; thread (r, qd) owns query row r, score cols {qd + 4*jj},
// and output columns {16k + 4qd + i : k=0..7, i=0..3}.
// Accumulator indices are COMPILE-TIME (k) -> registers; LDS addresses use
// qd only in the address (4 lanes -> banks {0,4,8,12}+16k, conflict-free).
__global__ void attn_kernel() {
    int qt = blockIdx.x;
    int h  = blockIdx.y;
    int b  = blockIdx.z;
    int kvh = h / (CH / CKVH);
    int tid = threadIdx.x;
    int r  = tid >> 2;          // 0..31
    int qd = tid & 3;           // 0..3
    __shared__ float Qs[32][132];
    __shared__ float KVs[32][132];
    __shared__ float Ss[32][33];

    for (int i = tid; i < 32 * 128; i += 128) {
        int rr = i >> 7, dd = i & 127;
        Qs[rr][dd] = g_q[((size_t)(b * CS + qt * 32 + rr) * CH + h) * CHD + dd];
    }
    float acc[32];
#pragma unroll
    for (int i = 0; i < 32; i++) acc[i] = 0.f;
    float m = -1e30f, l = 0.f;
    const float scale = 0.088388347648318447f;   // 1/sqrt(128)
    int qg = qt * 32 + r;

    for (int jt = 0; jt <= qt; jt++) {
        __syncthreads();
        for (int i = tid; i < 32 * 128; i += 128) {
            int rr = i >> 7, dd = i & 127;
            KVs[rr][dd] = g_k[((size_t)(b * CS + jt * 32 + rr) * CKVH + kvh) * CHD + dd];
        }
        __syncthreads();
        float sc[8];
#pragma unroll
        for (int jj = 0; jj < 8; jj++) sc[jj] = 0.f;
        const float4* q4 = (const float4*)&Qs[r][0];
        for (int d4 = 0; d4 < 32; d4++) {
            float4 qv = q4[d4];
#pragma unroll
            for (int jj = 0; jj < 8; jj++) {
                float4 kv = *(const float4*)&KVs[qd + 4 * jj][d4 * 4];
                sc[jj] += qv.x * kv.x + qv.y * kv.y + qv.z * kv.z + qv.w * kv.w;
            }
        }
        float lm = -1e30f;
        float p[8];
#pragma unroll
        for (int jj = 0; jj < 8; jj++) {
            int kg = jt * 32 + qd + 4 * jj;
            float v = sc[jj] * scale;
            if (kg > qg) v = -1e30f;
            p[jj] = v;
            lm = fmaxf(lm, v);
        }
        lm = fmaxf(lm, __shfl_xor_sync(0xffffffffu, lm, 1));
        lm = fmaxf(lm, __shfl_xor_sync(0xffffffffu, lm, 2));
        float tm = fmaxf(m, lm);
        float alpha = expf(m - tm);
        float lsum = 0.f;
#pragma unroll
        for (int jj = 0; jj < 8; jj++) { p[jj] = expf(p[jj] - tm); lsum += p[jj]; }
        lsum += __shfl_xor_sync(0xffffffffu, lsum, 1);
        lsum += __shfl_xor_sync(0xffffffffu, lsum, 2);
        l = l * alpha + lsum;
        m = tm;
#pragma unroll
        for (int jj = 0; jj < 8; jj++) Ss[r][qd + 4 * jj] = p[jj];
        __syncthreads();
        for (int i = tid; i < 32 * 128; i += 128) {
            int rr = i >> 7, dd = i & 127;
            KVs[rr][dd] = g_v[((size_t)(b * CS + jt * 32 + rr) * CKVH + kvh) * CHD + dd];
        }
        __syncthreads();
#pragma unroll
        for (int i = 0; i < 32; i++) acc[i] *= alpha;
        int cbase = qd * 4;   // thread's within-16 column offset
        for (int c = 0; c < 32; c++) {
            float pv = Ss[r][c];
#pragma unroll
            for (int k = 0; k < 8; k++) {
                float4 kv = *(const float4*)&KVs[c][k * 16 + cbase];
                acc[k * 4 + 0] += pv * kv.x;
                acc[k * 4 + 1] += pv * kv.y;
                acc[k * 4 + 2] += pv * kv.z;
                acc[k * 4 + 3] += pv * kv.w;
            }
        }
    }
    float inv = 1.f / l;
    int t = b * CS + qt * 32 + r;
    float* op = &g_o[((size_t)t * CH + h) * CHD];
#pragma unroll
    for (int k = 0; k < 8; k++) {
        float4 v;
        v.x = acc[k * 4 + 0] * inv;
        v.y = acc[k * 4 + 1] * inv;
        v.z = acc[k * 4 + 2] * inv;
        v.w = acc[k * 4 + 3] * inv;
        *(float4*)&op[k * 16 + qd * 4] = v;
    }
}

// ---------------- router softmax + top-8 ----------------
__global__ void topk_kernel() {
    int t = blockIdx.x, e = threadIdx.x;
    __shared__ float red[64];
    __shared__ int   redi[64];
    __shared__ float tv[8];
    __shared__ int   ti[8];
    float lg = g_logits[t * CE + e];
    red[e] = lg; __syncthreads();
    for (int st = 32; st > 0; st >>= 1) {
        if (e < st) red[e] = fmaxf(red[e], red[e + st]);
        __syncthreads();
    }
    float mx = red[0]; __syncthreads();
    float ex = expf(lg - mx);
    red[e] = ex; __syncthreads();
    for (int st = 32; st > 0; st >>= 1) {
        if (e < st) red[e] += red[e + st];
        __syncthreads();
    }
    float sum = red[0]; __syncthreads();
    float sel = ex / sum;
    for (int k = 0; k < 8; k++) {
        red[e] = sel; redi[e] = e; __syncthreads();
        for (int st = 32; st > 0; st >>= 1) {
            if (e < st) {
                if (red[e + st] > red[e]) { red[e] = red[e + st]; redi[e] = redi[e + st]; }
            }
            __syncthreads();
        }
        if (e == 0) { tv[k] = red[0]; ti[k] = redi[0]; }
        __syncthreads();
        if (e == ti[k]) sel = -1.f;
        __syncthreads();
    }
    if (e < 8) {
        float s8 = 0.f;
#pragma unroll
        for (int k = 0; k < 8; k++) s8 += tv[k];
        g_topi[t * CK + e] = ti[e];
        g_topw[t * CK + e] = tv[e] / s8;
    }
}

// ---------------- routing bookkeeping ----------------
__global__ void zero_counts_kernel() { if (threadIdx.x < CE) g_counts[threadIdx.x] = 0; }

__global__ void count_kernel() {
    int i = blockIdx.x * blockDim.x + threadIdx.x;
    if (i < NSLOT) atomicAdd(&g_counts[g_topi[i]], 1);
}

__global__ void scan_kernel() {
    int acc = 0;
    for (int e = 0; e < CE; e++) {
        g_offsets[e] = acc;
        g_cursor[e]  = acc;
        acc += ((g_counts[e] + 127) >> 7) << 7;
    }
}

__global__ void init_slots_kernel() {
    int i = blockIdx.x * blockDim.x + threadIdx.x;
    if (i < PADTOT) g_slot_token[i] = 0;
}

__global__ void fill_kernel() {
    int i = blockIdx.x * blockDim.x + threadIdx.x;
    if (i < NSLOT) {
        int e = g_topi[i];
        int p = atomicAdd(&g_cursor[e], 1);
        g_slot_token[p] = i >> 3;
        g_pos_of[i] = p;
    }
}

// ================= unified MoE bf16 GEMM, BK=32 (2 CTAs/SM; R4-proven) =====
constexpr int SM_MOE = 38400;

template<int MODE>
__global__ __launch_bounds__(256, 2)
void moe_gemm_bf16(const float* __restrict__ W) {
    extern __shared__ char smraw[];
    __nv_bfloat16 (*As)[128][40] = (__nv_bfloat16(*)[128][40])smraw;
    __nv_bfloat16 (*Bs)[32][72]  = (__nv_bfloat16(*)[32][72])(smraw + 20480);
    int* stok = (int*)(smraw + 29696);
    float (*scr)[16][16] = (float(*)[16][16])(smraw + 30208);

    constexpr int KDIM = (MODE == 2) ? CF : CD;
    constexpr int NDIM = (MODE == 2) ? CD : CF;

    int e = blockIdx.y;
    int n0 = blockIdx.x * 64;
    int off = g_offsets[e], cnt = g_counts[e];
    int ntiles = (cnt + 127) >> 7;
    const float* Bm = W + (size_t)e * KDIM * NDIM;

    int tid = threadIdx.x;
    int w = tid >> 5, wm = w & 3, wn = w >> 2;
    int lane = tid & 31;
    int b_row = tid >> 4, b_c4 = (tid & 15) * 4;

    for (int rt = 0; rt < ntiles; rt++) {
        size_t abase = (size_t)(off + rt * 128);
        if (MODE < 2) {
            if (tid < 128) stok[tid] = g_slot_token[abase + tid];
            __syncthreads();
        }

        FragCB acc[2][2];
#pragma unroll
        for (int i = 0; i < 2; i++)
#pragma unroll
            for (int j = 0; j < 2; j++) wmma::fill_fragment(acc[i][j], 0.f);

        uint4 raA[2]; float4 rb[2];
        constexpr int nk = KDIM / 32;
#pragma unroll
        for (int it = 0; it < 2; it++) {
            int i = tid + it * 256;
            int row = i >> 2, c8 = (i & 3) * 8;
            if (MODE < 2)
                raA[it] = *(const uint4*)&g_ht_bf[(size_t)stok[row] * CD + c8];
            else
                raA[it] = *(const uint4*)&g_act_bf[(abase + row) * CF + c8];
        }
#pragma unroll
        for (int it = 0; it < 2; it++)
            rb[it] = *(const float4*)&Bm[(size_t)(b_row + it * 16) * NDIM + n0 + b_c4];
#pragma unroll
        for (int it = 0; it < 2; it++) {
            int i = tid + it * 256;
            int row = i >> 2, c8 = (i & 3) * 8;
            *(uint4*)&As[0][row][c8] = raA[it];
        }
#pragma unroll
        for (int it = 0; it < 2; it++)
            st_bf4(&Bs[0][b_row + it * 16][b_c4], rb[it]);
        __syncthreads();

        for (int k = 0; k < nk; k++) {
            int cur = k & 1;
            if (k + 1 < nk) {
                int k0 = (k + 1) * 32;
#pragma unroll
                for (int it = 0; it < 2; it++) {
                    int i = tid + it * 256;
                    int row = i >> 2, c8 = (i & 3) * 8;
                    if (MODE < 2)
                        raA[it] = *(const uint4*)&g_ht_bf[(size_t)stok[row] * CD + k0 + c8];
                    else
                        raA[it] = *(const uint4*)&g_act_bf[(abase + row) * CF + k0 + c8];
                }
#pragma unroll
                for (int it = 0; it < 2; it++)
                    rb[it] = *(const float4*)&Bm[(size_t)(k0 + b_row + it * 16) * NDIM + n0 + b_c4];
            }
#pragma unroll
            for (int kk = 0; kk < 2; kk++) {
                FragAB a[2]; FragBB b[2];
#pragma unroll
                for (int i = 0; i < 2; i++)
                    wmma::load_matrix_sync(a[i], &As[cur][wm * 32 + i * 16][kk * 16], 40);
#pragma unroll
                for (int j = 0; j < 2; j++)
                    wmma::load_matrix_sync(b[j], &Bs[cur][kk * 16][wn * 32 + j * 16], 72);
#pragma unroll
                for (int i = 0; i < 2; i++)
#pragma unroll
                    for (int j = 0; j < 2; j++) wmma::mma_sync(acc[i][j], a[i], b[j], acc[i][j]);
            }
            if (k + 1 < nk) {
                int nxt = cur ^ 1;
#pragma unroll
                for (int it = 0; it < 2; it++) {
                    int i = tid + it * 256;
                    int row = i >> 2, c8 = (i & 3) * 8;
                    *(uint4*)&As[nxt][row][c8] = raA[it];
                }
#pragma unroll
                for (int it = 0; it < 2; it++)
                    st_bf4(&Bs[nxt][b_row + it * 16][b_c4], rb[it]);
            }
            __syncthreads();
        }

        if (MODE == 0) {
#pragma unroll
            for (int i = 0; i < 2; i++)
#pragma unroll
                for (int j = 0; j < 2; j++) {
                    float* cp = g_gate + (abase + wm * 32 + i * 16) * CF + n0 + wn * 32 + j * 16;
                    wmma::store_matrix_sync(cp, acc[i][j], CF, wmma::mem_row_major);
                }
        } else if (MODE == 2) {
#pragma unroll
            for (int i = 0; i < 2; i++)
#pragma unroll
                for (int j = 0; j < 2; j++) {
                    float* cp = g_y + (abase + wm * 32 + i * 16) * CD + n0 + wn * 32 + j * 16;
                    wmma::store_matrix_sync(cp, acc[i][j], CD, wmma::mem_row_major);
                }
        } else {
#pragma unroll
            for (int i = 0; i < 2; i++)
#pragma unroll
                for (int j = 0; j < 2; j++) {
                    wmma::store_matrix_sync(&scr[w][0][0], acc[i][j], 16, wmma::mem_row_major);
                    __syncwarp();
                    {
                        int r = lane >> 1, cb = (lane & 1) * 8;
                        size_t grow = abase + wm * 32 + i * 16 + r;
                        int col = n0 + wn * 32 + j * 16 + cb;
                        const float* gp = &g_gate[grow * CF + col];
                        float4 g0 = *(const float4*)gp;
                        float4 g1 = *(const float4*)(gp + 4);
                        float4 u0 = *(float4*)&scr[w][r][cb];
                        float4 u1 = *(float4*)&scr[w][r][cb + 4];
                        float4 o0, o1;
                        o0.x = (g0.x / (1.f + expf(-g0.x))) * u0.x;
                        o0.y = (g0.y / (1.f + expf(-g0.y))) * u0.y;
                        o0.z = (g0.z / (1.f + expf(-g0.z))) * u0.z;
                        o0.w = (g0.w / (1.f + expf(-g0.w))) * u0.w;
                        o1.x = (g1.x / (1.f + expf(-g1.x))) * u1.x;
                        o1.y = (g1.y / (1.f + expf(-g1.y))) * u1.y;
                        o1.z = (g1.z / (1.f + expf(-g1.z))) * u1.z;
                        o1.w = (g1.w / (1.f + expf(-g1.w))) * u1.w;
                        __nv_bfloat16* dst = g_act_bf + grow * CF + col;
                        st_bf4(dst, o0);
                        st_bf4(dst + 4, o1);
                    }
                    __syncwarp();
                }
        }
        __syncthreads();
    }
}

// ---------------- final combine ----------------
__global__ void final_add_kernel(float* __restrict__ out) {
    int t = blockIdx.x;
    __shared__ int   pos[8];
    __shared__ float w[8];
    if (threadIdx.x < 8) {
        pos[threadIdx.x] = g_pos_of[t * CK + threadIdx.x];
        w[threadIdx.x]   = g_topw[t * CK + threadIdx.x];
    }
    __syncthreads();
    for (int d = threadIdx.x; d < CD; d += 256) {
        float acc = out[(size_t)t * CD + d];
#pragma unroll
        for (int k = 0; k < 8; k++)
            acc += w[k] * g_y[(size_t)pos[k] * CD + d];
        out[(size_t)t * CD + d] = acc;
    }
}

// ---------------- launch ----------------
extern "C" void kernel_launch(void* const* d_in, const int* in_sizes, int n_in,
                              void* d_out, int out_size) {
    const float* x        = (const float*)d_in[0];
    const float* cos_     = (const float*)d_in[1];
    const float* sin_     = (const float*)d_in[2];
    const float* ln1_w    = (const float*)d_in[3];
    const float* wq       = (const float*)d_in[4];
    const float* wk       = (const float*)d_in[5];
    const float* wv       = (const float*)d_in[6];
    const float* wo       = (const float*)d_in[7];
    const float* qn_w     = (const float*)d_in[8];
    const float* kn_w     = (const float*)d_in[9];
    const float* ln2_w    = (const float*)d_in[10];
    const float* router_w = (const float*)d_in[11];
    const float* w_gate   = (const float*)d_in[12];
    const float* w_up     = (const float*)d_in[13];
    const float* w_down   = (const float*)d_in[14];
    float* out = (float*)d_out;

    cudaFuncSetAttribute(gemm_tf32_pipe,   cudaFuncAttributeMaxDynamicSharedMemorySize, SM_TF32);
    cudaFuncSetAttribute(qkv_tf32,         cudaFuncAttributeMaxDynamicSharedMemorySize, SM_TF32);
    cudaFuncSetAttribute(moe_gemm_bf16<0>, cudaFuncAttributeMaxDynamicSharedMemorySize, SM_MOE);
    cudaFuncSetAttribute(moe_gemm_bf16<1>, cudaFuncAttributeMaxDynamicSharedMemorySize, SM_MOE);
    cudaFuncSetAttribute(moe_gemm_bf16<2>, cudaFuncAttributeMaxDynamicSharedMemorySize, SM_MOE);

    float *p_h, *p_o, *p_ht, *p_logits;
    __nv_bfloat16 *p_ht_bf;
    cudaGetSymbolAddress((void**)&p_h,  g_h);
    cudaGetSymbolAddress((void**)&p_o,  g_o);
    cudaGetSymbolAddress((void**)&p_ht, g_ht);
    cudaGetSymbolAddress((void**)&p_ht_bf, g_ht_bf);
    cudaGetSymbolAddress((void**)&p_logits, g_logits);

    // 1. h = rmsnorm(x)
    rmsnorm_kernel<<<CT, 256>>>(x, ln1_w, p_h);
    // 2. fused q,k,v projections (one launch, 768 blocks)
    qkv_tf32<<<dim3(48, CT / 128), 256, SM_TF32>>>(p_h, wq, wk, wv);
    // 3. per-head q/k rmsnorm + rope
    qknorm_rope_kernel<<<dim3(CT, CH + CKVH), 128>>>(cos_, sin_, qn_w, kn_w);
    // 4. attention (exact fp32, register-resident accumulators)
    attn_kernel<<<dim3(CS / 32, CH, CB), 128>>>();
    // 5. out = o @ wo + x
    gemm_tf32_pipe<<<dim3(CD / 64, CT / 128), 256, SM_TF32>>>(p_o, wo, x, out, CD, CD);
    // 6. ht = rmsnorm(out), fp32 + bf16
    rmsnorm_bf_kernel<<<CT, 256>>>(out, ln2_w, p_ht, p_ht_bf);
    // 7. router logits (exact fp32) + top-8
    gemm64<<<dim3(CE / 64, CT / 64), 256>>>(p_ht, router_w, nullptr, p_logits, CT, CE, CD);
    topk_kernel<<<CT, 64>>>();
    // 8. routing bookkeeping
    zero_counts_kernel<<<1, 64>>>();
    count_kernel<<<NSLOT / 256, 256>>>();
    scan_kernel<<<1, 1>>>();
    init_slots_kernel<<<PADTOT / 256, 256>>>();
    fill_kernel<<<NSLOT / 256, 256>>>();
    // 9. MoE: gate, up(+silu), down (bf16 BK=32, 2 CTAs/SM — R4-proven)
    moe_gemm_bf16<0><<<dim3(CF / 64, CE), 256, SM_MOE>>>(w_gate);
    moe_gemm_bf16<1><<<dim3(CF / 64, CE), 256, SM_MOE>>>(w_up);
    moe_gemm_bf16<2><<<dim3(CD / 64, CE), 256, SM_MOE>>>(w_down);
    // 10. deterministic per-token combine
    final_add_kernel<<<CT, 256>>>(out);
}

// round 9
// speedup vs baseline: 3.2909x; 1.2051x over previous
#include <cuda_runtime.h>
#include <cuda_bf16.h>
#include <math.h>
#include <mma.h>
using namespace nvcuda;

// ---------------- problem constants ----------------
constexpr int CB  = 2;
constexpr int CS  = 1024;
constexpr int CD  = 2048;
constexpr int CH  = 16;
constexpr int CKVH= 4;
constexpr int CHD = 128;
constexpr int CE  = 64;
constexpr int CK  = 8;
constexpr int CF  = 768;
constexpr int CT  = CB * CS;             // 2048
constexpr float CEPS = 1e-6f;
constexpr int NSLOT = CT * CK;           // 16384
constexpr int PADTOT = NSLOT + CE * 128; // 24576

// ---------------- scratch ----------------
__device__ float g_h   [CT * CD];
__device__ float g_q   [CT * CH  * CHD];
__device__ float g_k   [CT * CKVH* CHD];
__device__ float g_v   [CT * CKVH* CHD];
__device__ float g_o   [CT * CH  * CHD];
__device__ float g_ht  [CT * CD];
__device__ __nv_bfloat16 g_ht_bf[CT * CD];
__device__ float g_logits[CT * CE];
__device__ int   g_topi[CT * CK];
__device__ float g_topw[CT * CK];
__device__ int   g_counts[CE];
__device__ int   g_offsets[CE];
__device__ int   g_cursor[CE];
__device__ int   g_slot_token[PADTOT];
__device__ int   g_pos_of[NSLOT];
__device__ float g_gate[(size_t)PADTOT * CF];
__device__ __nv_bfloat16 g_act_bf[(size_t)PADTOT * CF];
__device__ float g_y   [(size_t)PADTOT * CD];

// ---------------- helpers ----------------
__device__ __forceinline__ void st_bf4(__nv_bfloat16* p, float4 v) {
    __nv_bfloat162 lo = __floats2bfloat162_rn(v.x, v.y);
    __nv_bfloat162 hi = __floats2bfloat162_rn(v.z, v.w);
    uint2 u;
    u.x = *(unsigned int*)&lo;
    u.y = *(unsigned int*)&hi;
    *(uint2*)p = u;
}

__device__ __forceinline__ unsigned int f2tf32(float x) {
    unsigned int r;
    asm("cvt.rna.tf32.f32 %0, %1;" : "=r"(r) : "f"(x));
    return r;
}

__device__ __forceinline__ void mma_tf32(float* c, unsigned int a0, unsigned int a1,
                                         unsigned int a2, unsigned int a3,
                                         unsigned int b0, unsigned int b1) {
    asm volatile(
        "mma.sync.aligned.m16n8k8.row.col.f32.tf32.tf32.f32 "
        "{%0,%1,%2,%3}, {%4,%5,%6,%7}, {%8,%9}, {%0,%1,%2,%3};"
        : "+f"(c[0]), "+f"(c[1]), "+f"(c[2]), "+f"(c[3])
        : "r"(a0), "r"(a1), "r"(a2), "r"(a3), "r"(b0), "r"(b1));
}

// ---------------- rmsnorm ----------------
__global__ void rmsnorm_kernel(const float* __restrict__ in,
                               const float* __restrict__ w,
                               float* __restrict__ out) {
    int t = blockIdx.x;
    const float* row = in + (size_t)t * CD;
    float ss = 0.f;
    for (int d = threadIdx.x; d < CD; d += 256) { float v = row[d]; ss += v * v; }
    __shared__ float red[256];
    red[threadIdx.x] = ss; __syncthreads();
    for (int st = 128; st > 0; st >>= 1) {
        if (threadIdx.x < st) red[threadIdx.x] += red[threadIdx.x + st];
        __syncthreads();
    }
    float scale = rsqrtf(red[0] / (float)CD + CEPS);
    for (int d = threadIdx.x; d < CD; d += 256)
        out[(size_t)t * CD + d] = row[d] * scale * w[d];
}

__global__ void rmsnorm_bf_kernel(const float* __restrict__ in,
                                  const float* __restrict__ w,
                                  float* __restrict__ out,
                                  __nv_bfloat16* __restrict__ outb) {
    int t = blockIdx.x;
    const float* row = in + (size_t)t * CD;
    float ss = 0.f;
    for (int d = threadIdx.x; d < CD; d += 256) { float v = row[d]; ss += v * v; }
    __shared__ float red[256];
    red[threadIdx.x] = ss; __syncthreads();
    for (int st = 128; st > 0; st >>= 1) {
        if (threadIdx.x < st) red[threadIdx.x] += red[threadIdx.x + st];
        __syncthreads();
    }
    float scale = rsqrtf(red[0] / (float)CD + CEPS);
    for (int d = threadIdx.x; d < CD; d += 256) {
        float v = row[d] * scale * w[d];
        out[(size_t)t * CD + d] = v;
        outb[(size_t)t * CD + d] = __float2bfloat16(v);
    }
}

// ---------------- scalar GEMM (router: exact fp32 feeds top-k) -------
__global__ void gemm64(const float* __restrict__ A, const float* __restrict__ Bm,
                       const float* __restrict__ res, float* __restrict__ C,
                       int M, int N, int K) {
    __shared__ float As[16][65];
    __shared__ float Bs[16][64];
    int tid = threadIdx.x;
    int tx = tid & 15, ty = tid >> 4;
    int m0 = blockIdx.y * 64, n0 = blockIdx.x * 64;
    int arow = tid >> 2;
    int acol = (tid & 3) * 4;
    int blin = tid * 4;
    int brow = blin >> 6;
    int bcol = blin & 63;
    const float* Aptr = A + (size_t)(m0 + arow) * K + acol;
    const float* Bptr = Bm + (size_t)brow * N + n0 + bcol;
    float acc[4][4] = {};
    for (int k0 = 0; k0 < K; k0 += 16) {
        float4 av = *(const float4*)(Aptr + k0);
        float4 bv = *(const float4*)(Bptr + (size_t)k0 * N);
        As[acol + 0][arow] = av.x; As[acol + 1][arow] = av.y;
        As[acol + 2][arow] = av.z; As[acol + 3][arow] = av.w;
        *(float4*)&Bs[brow][bcol] = bv;
        __syncthreads();
#pragma unroll
        for (int kk = 0; kk < 16; kk++) {
            float a[4], b[4];
#pragma unroll
            for (int i = 0; i < 4; i++) a[i] = As[kk][ty * 4 + i];
#pragma unroll
            for (int j = 0; j < 4; j++) b[j] = Bs[kk][tx * 4 + j];
#pragma unroll
            for (int i = 0; i < 4; i++)
#pragma unroll
                for (int j = 0; j < 4; j++) acc[i][j] += a[i] * b[j];
        }
        __syncthreads();
    }
#pragma unroll
    for (int i = 0; i < 4; i++)
#pragma unroll
        for (int j = 0; j < 4; j++) {
            size_t idx = (size_t)(m0 + ty * 4 + i) * N + n0 + tx * 4 + j;
            C[idx] = acc[i][j] + (res ? res[idx] : 0.f);
        }
}

// ---------------- fragment types ----------------
using FragAT = wmma::fragment<wmma::matrix_a, 16, 16, 8, wmma::precision::tf32, wmma::row_major>;
using FragBT = wmma::fragment<wmma::matrix_b, 16, 16, 8, wmma::precision::tf32, wmma::row_major>;
using FragAB = wmma::fragment<wmma::matrix_a, 16, 16, 16, __nv_bfloat16, wmma::row_major>;
using FragBB = wmma::fragment<wmma::matrix_b, 16, 16, 16, __nv_bfloat16, wmma::row_major>;
using FragC  = wmma::fragment<wmma::accumulator, 16, 16, 8, float>;
using FragCB = wmma::fragment<wmma::accumulator, 16, 16, 16, float>;

__device__ __forceinline__ void ld_at(FragAT& f, const float* p, int ld) {
    wmma::load_matrix_sync(f, p, ld);
#pragma unroll
    for (int i = 0; i < f.num_elements; i++) f.x[i] = wmma::__float_to_tf32(f.x[i]);
}
__device__ __forceinline__ void ld_bt(FragBT& f, const float* p, int ld) {
    wmma::load_matrix_sync(f, p, ld);
#pragma unroll
    for (int i = 0; i < f.num_elements; i++) f.x[i] = wmma::__float_to_tf32(f.x[i]);
}

// ================= TF32 dense GEMM body (shared by qkv + generic) =======
constexpr int SM_TF32 = 2*128*36*4 + 2*32*68*4;   // 54272

__device__ __forceinline__
void gemm_tf32_body(char* smraw, const float* __restrict__ A, const float* __restrict__ B,
                    const float* __restrict__ res, float* __restrict__ C,
                    int N, int K, int m0, int n0) {
    float (*As)[128][36] = (float(*)[128][36])smraw;
    float (*Bs)[32][68]  = (float(*)[32][68])(smraw + 2*128*36*4);
    int tid = threadIdx.x;
    int w = tid >> 5, wm = w & 3, wn = w >> 2;

    int a_row = tid >> 3, a_c4 = (tid & 7) * 4;
    int b_row = tid >> 4, b_c4 = (tid & 15) * 4;

    FragC acc[2][2];
#pragma unroll
    for (int i = 0; i < 2; i++)
#pragma unroll
        for (int j = 0; j < 2; j++) wmma::fill_fragment(acc[i][j], 0.f);

    float4 ra[4], rb[2];
    int nk = K / 32;
#pragma unroll
    for (int it = 0; it < 4; it++)
        ra[it] = *(const float4*)&A[(size_t)(m0 + a_row + it * 32) * K + a_c4];
#pragma unroll
    for (int it = 0; it < 2; it++)
        rb[it] = *(const float4*)&B[(size_t)(b_row + it * 16) * N + n0 + b_c4];
#pragma unroll
    for (int it = 0; it < 4; it++) *(float4*)&As[0][a_row + it * 32][a_c4] = ra[it];
#pragma unroll
    for (int it = 0; it < 2; it++) *(float4*)&Bs[0][b_row + it * 16][b_c4] = rb[it];
    __syncthreads();

    for (int k = 0; k < nk; k++) {
        int cur = k & 1;
        if (k + 1 < nk) {
            int k0 = (k + 1) * 32;
#pragma unroll
            for (int it = 0; it < 4; it++)
                ra[it] = *(const float4*)&A[(size_t)(m0 + a_row + it * 32) * K + k0 + a_c4];
#pragma unroll
            for (int it = 0; it < 2; it++)
                rb[it] = *(const float4*)&B[(size_t)(k0 + b_row + it * 16) * N + n0 + b_c4];
        }
#pragma unroll
        for (int kk = 0; kk < 4; kk++) {
            FragAT a[2]; FragBT b[2];
#pragma unroll
            for (int i = 0; i < 2; i++) ld_at(a[i], &As[cur][wm * 32 + i * 16][kk * 8], 36);
#pragma unroll
            for (int j = 0; j < 2; j++) ld_bt(b[j], &Bs[cur][kk * 8][wn * 32 + j * 16], 68);
#pragma unroll
            for (int i = 0; i < 2; i++)
#pragma unroll
                for (int j = 0; j < 2; j++) wmma::mma_sync(acc[i][j], a[i], b[j], acc[i][j]);
        }
        if (k + 1 < nk) {
            int nxt = cur ^ 1;
#pragma unroll
            for (int it = 0; it < 4; it++) *(float4*)&As[nxt][a_row + it * 32][a_c4] = ra[it];
#pragma unroll
            for (int it = 0; it < 2; it++) *(float4*)&Bs[nxt][b_row + it * 16][b_c4] = rb[it];
        }
        __syncthreads();
    }
#pragma unroll
    for (int i = 0; i < 2; i++)
#pragma unroll
        for (int j = 0; j < 2; j++) {
            size_t co = (size_t)(m0 + wm * 32 + i * 16) * N + n0 + wn * 32 + j * 16;
            if (res) {
                FragC r;
                wmma::load_matrix_sync(r, res + co, N, wmma::mem_row_major);
#pragma unroll
                for (int e2 = 0; e2 < r.num_elements; e2++) acc[i][j].x[e2] += r.x[e2];
            }
            wmma::store_matrix_sync(C + co, acc[i][j], N, wmma::mem_row_major);
        }
}

__global__ __launch_bounds__(256, 2)
void gemm_tf32_pipe(const float* __restrict__ A, const float* __restrict__ B,
                    const float* __restrict__ res, float* __restrict__ C,
                    int N, int K) {
    extern __shared__ char smraw[];
    gemm_tf32_body(smraw, A, B, res, C, N, K, blockIdx.y * 128, blockIdx.x * 64);
}

// fused QKV projection: one launch, 48 n-tiles (32 Q + 8 K + 8 V)
__global__ __launch_bounds__(256, 2)
void qkv_tf32(const float* __restrict__ A,
              const float* __restrict__ wq, const float* __restrict__ wk,
              const float* __restrict__ wv) {
    extern __shared__ char smraw[];
    int nt = blockIdx.x;
    const float* B; float* C; int N, n0;
    if (nt < 32)      { B = wq; C = g_q; N = CH  * CHD; n0 = nt * 64; }
    else if (nt < 40) { B = wk; C = g_k; N = CKVH* CHD; n0 = (nt - 32) * 64; }
    else              { B = wv; C = g_v; N = CKVH* CHD; n0 = (nt - 40) * 64; }
    gemm_tf32_body(smraw, A, B, nullptr, C, N, CD, blockIdx.y * 128, n0);
}

// ---------------- per-head q/k rmsnorm + rope ----------------
__global__ void qknorm_rope_kernel(const float* __restrict__ cos_,
                                   const float* __restrict__ sin_,
                                   const float* __restrict__ qn_w,
                                   const float* __restrict__ kn_w) {
    int t = blockIdx.x;
    int hy = blockIdx.y;
    int d = threadIdx.x;
    float* ptr; const float* w;
    if (hy < CH) { ptr = g_q + ((size_t)t * CH + hy) * CHD;          w = qn_w; }
    else         { ptr = g_k + ((size_t)t * CKVH + (hy - CH)) * CHD; w = kn_w; }
    float v = ptr[d];
    float ss = v * v;
#pragma unroll
    for (int off = 16; off > 0; off >>= 1) ss += __shfl_xor_sync(0xffffffffu, ss, off);
    __shared__ float ws[4];
    if ((d & 31) == 0) ws[d >> 5] = ss;
    __syncthreads();
    float tot = ws[0] + ws[1] + ws[2] + ws[3];
    float nrm = v * rsqrtf(tot / (float)CHD + CEPS) * w[d];
    __shared__ float nbuf[128];
    nbuf[d] = nrm;
    __syncthreads();
    float rot = (d < 64) ? -nbuf[d + 64] : nbuf[d - 64];
    float c = cos_[(size_t)t * CHD + d];
    float s = sin_[(size_t)t * CHD + d];
    ptr[d] = nrm * c + rot * s;
}

// ================= flash attention v3: tf32 mma.sync (FA2 structure) =====
// 64 q rows per block, 4 warps (warp w owns rows 16w..16w+15), 32-kv tiles.
// m16n8k8: C rows = lane>>2, (lane>>2)+8; cols = 2*(lane&3)+{0,1}.
// smem: Qs[64][132] | KVs[32][132] | Ss[64][36]  (fp32)
constexpr int SM_ATTN = (64*132 + 32*132 + 64*36) * 4;   // 59904

__global__ void attn_kernel_mma() {
    extern __shared__ char sm[];
    float (*Qs)[132] = (float(*)[132])sm;
    float (*KVs)[132] = (float(*)[132])(sm + 64*132*4);
    float (*Ss)[36]  = (float(*)[36])(sm + (64+32)*132*4);

    int qt = blockIdx.x;       // 0..15 (64-row q tiles)
    int h  = blockIdx.y;
    int b  = blockIdx.z;
    int kvh = h / (CH / CKVH);
    int tid = threadIdx.x;
    int w = tid >> 5, lane = tid & 31;
    int gi = lane >> 2;        // 0..7
    int li = lane & 3;         // 0..3

    // load Q tile (64 x 128)
    for (int i = tid; i < 64 * 32; i += 128) {
        int rr = i >> 5, c4 = (i & 31) * 4;
        *(float4*)&Qs[rr][c4] =
            *(const float4*)&g_q[((size_t)(b * CS + qt * 64 + rr) * CH + h) * CHD + c4];
    }

    float o[64];               // 16 n-tiles x 4 regs
#pragma unroll
    for (int i = 0; i < 64; i++) o[i] = 0.f;
    float m0 = -1e30f, m1 = -1e30f, l0 = 0.f, l1 = 0.f;
    const float scale = 0.088388347648318447f;   // 1/sqrt(128)
    int r0g = qt * 64 + w * 16 + gi;             // global q row (c0/c1)
    int r1g = r0g + 8;

    int jmax = 2 * qt + 1;
    for (int jt = 0; jt <= jmax; jt++) {
        __syncthreads();
        for (int i = tid; i < 32 * 32; i += 128) {
            int rr = i >> 5, c4 = (i & 31) * 4;
            *(float4*)&KVs[rr][c4] =
                *(const float4*)&g_k[((size_t)(b * CS + jt * 32 + rr) * CKVH + kvh) * CHD + c4];
        }
        __syncthreads();

        // S_w(16x32) = Q_w(16x128) @ K^T
        float sacc[4][4];
#pragma unroll
        for (int n = 0; n < 4; n++)
#pragma unroll
            for (int i = 0; i < 4; i++) sacc[n][i] = 0.f;
#pragma unroll
        for (int k8 = 0; k8 < 16; k8++) {
            unsigned int a0 = f2tf32(Qs[w * 16 + gi][k8 * 8 + li]);
            unsigned int a1 = f2tf32(Qs[w * 16 + gi + 8][k8 * 8 + li]);
            unsigned int a2 = f2tf32(Qs[w * 16 + gi][k8 * 8 + li + 4]);
            unsigned int a3 = f2tf32(Qs[w * 16 + gi + 8][k8 * 8 + li + 4]);
#pragma unroll
            for (int n = 0; n < 4; n++) {
                unsigned int b0 = f2tf32(KVs[n * 8 + gi][k8 * 8 + li]);
                unsigned int b1 = f2tf32(KVs[n * 8 + gi][k8 * 8 + li + 4]);
                mma_tf32(sacc[n], a0, a1, a2, a3, b0, b1);
            }
        }

        // scale + causal mask + online softmax (rows r0g, r1g)
        float lm0 = -1e30f, lm1 = -1e30f;
#pragma unroll
        for (int n = 0; n < 4; n++) {
            int c0 = jt * 32 + n * 8 + 2 * li;
#pragma unroll
            for (int i = 0; i < 2; i++) {
                float v0 = sacc[n][i] * scale;
                float v1 = sacc[n][i + 2] * scale;
                if (c0 + i > r0g) v0 = -1e30f;
                if (c0 + i > r1g) v1 = -1e30f;
                sacc[n][i] = v0; sacc[n][i + 2] = v1;
                lm0 = fmaxf(lm0, v0); lm1 = fmaxf(lm1, v1);
            }
        }
        lm0 = fmaxf(lm0, __shfl_xor_sync(0xffffffffu, lm0, 1));
        lm0 = fmaxf(lm0, __shfl_xor_sync(0xffffffffu, lm0, 2));
        lm1 = fmaxf(lm1, __shfl_xor_sync(0xffffffffu, lm1, 1));
        lm1 = fmaxf(lm1, __shfl_xor_sync(0xffffffffu, lm1, 2));
        float tm0 = fmaxf(m0, lm0), tm1 = fmaxf(m1, lm1);
        float al0 = expf(m0 - tm0), al1 = expf(m1 - tm1);
        float ls0 = 0.f, ls1 = 0.f;
#pragma unroll
        for (int n = 0; n < 4; n++) {
#pragma unroll
            for (int i = 0; i < 2; i++) {
                float p0 = expf(sacc[n][i] - tm0);
                float p1 = expf(sacc[n][i + 2] - tm1);
                sacc[n][i] = p0; sacc[n][i + 2] = p1;
                ls0 += p0; ls1 += p1;
            }
        }
        ls0 += __shfl_xor_sync(0xffffffffu, ls0, 1);
        ls0 += __shfl_xor_sync(0xffffffffu, ls0, 2);
        ls1 += __shfl_xor_sync(0xffffffffu, ls1, 1);
        ls1 += __shfl_xor_sync(0xffffffffu, ls1, 2);
        l0 = l0 * al0 + ls0;
        l1 = l1 * al1 + ls1;
        m0 = tm0; m1 = tm1;

        // stash P to smem (own warp stripe only)
#pragma unroll
        for (int n = 0; n < 4; n++) {
            Ss[w * 16 + gi][n * 8 + 2 * li]         = sacc[n][0];
            Ss[w * 16 + gi][n * 8 + 2 * li + 1]     = sacc[n][1];
            Ss[w * 16 + gi + 8][n * 8 + 2 * li]     = sacc[n][2];
            Ss[w * 16 + gi + 8][n * 8 + 2 * li + 1] = sacc[n][3];
        }

        // rescale O accumulators
#pragma unroll
        for (int n = 0; n < 16; n++) {
            o[n * 4 + 0] *= al0; o[n * 4 + 1] *= al0;
            o[n * 4 + 2] *= al1; o[n * 4 + 3] *= al1;
        }

        __syncthreads();   // all warps done reading K
        for (int i = tid; i < 32 * 32; i += 128) {
            int rr = i >> 5, c4 = (i & 31) * 4;
            *(float4*)&KVs[rr][c4] =
                *(const float4*)&g_v[((size_t)(b * CS + jt * 32 + rr) * CKVH + kvh) * CHD + c4];
        }
        __syncwarp();      // own Ss stripe written above, read below (same warp)
        __syncthreads();   // V ready

        // O_w(16x128) += P_w(16x32) @ V(32x128)
#pragma unroll
        for (int k8 = 0; k8 < 4; k8++) {
            unsigned int a0 = f2tf32(Ss[w * 16 + gi][k8 * 8 + li]);
            unsigned int a1 = f2tf32(Ss[w * 16 + gi + 8][k8 * 8 + li]);
            unsigned int a2 = f2tf32(Ss[w * 16 + gi][k8 * 8 + li + 4]);
            unsigned int a3 = f2tf32(Ss[w * 16 + gi + 8][k8 * 8 + li + 4]);
#pragma unroll
            for (int n = 0; n < 16; n++) {
                unsigned int b0 = f2tf32(KVs[k8 * 8 + li][n * 8 + gi]);
                unsigned int b1 = f2tf32(KVs[k8 * 8 + li + 4][n * 8 + gi]);
                mma_tf32(&o[n * 4], a0, a1, a2, a3, b0, b1);
            }
        }
    }

    // epilogue: divide by l, store
    float inv0 = 1.f / l0, inv1 = 1.f / l1;
    int t0 = b * CS + r0g, t1 = b * CS + r1g;
    float* op0 = &g_o[((size_t)t0 * CH + h) * CHD];
    float* op1 = &g_o[((size_t)t1 * CH + h) * CHD];
#pragma unroll
    for (int n = 0; n < 16; n++) {
        int col = n * 8 + 2 * li;
        float2 v0 = make_float2(o[n * 4 + 0] * inv0, o[n * 4 + 1] * inv0);
        float2 v1 = make_float2(o[n * 4 + 2] * inv1, o[n * 4 + 3] * inv1);
        *(float2*)&op0[col] = v0;
        *(float2*)&op1[col] = v1;
    }
}

// ---------------- router softmax + top-8 ----------------
__global__ void topk_kernel() {
    int t = blockIdx.x, e = threadIdx.x;
    __shared__ float red[64];
    __shared__ int   redi[64];
    __shared__ float tv[8];
    __shared__ int   ti[8];
    float lg = g_logits[t * CE + e];
    red[e] = lg; __syncthreads();
    for (int st = 32; st > 0; st >>= 1) {
        if (e < st) red[e] = fmaxf(red[e], red[e + st]);
        __syncthreads();
    }
    float mx = red[0]; __syncthreads();
    float ex = expf(lg - mx);
    red[e] = ex; __syncthreads();
    for (int st = 32; st > 0; st >>= 1) {
        if (e < st) red[e] += red[e + st];
        __syncthreads();
    }
    float sum = red[0]; __syncthreads();
    float sel = ex / sum;
    for (int k = 0; k < 8; k++) {
        red[e] = sel; redi[e] = e; __syncthreads();
        for (int st = 32; st > 0; st >>= 1) {
            if (e < st) {
                if (red[e + st] > red[e]) { red[e] = red[e + st]; redi[e] = redi[e + st]; }
            }
            __syncthreads();
        }
        if (e == 0) { tv[k] = red[0]; ti[k] = redi[0]; }
        __syncthreads();
        if (e == ti[k]) sel = -1.f;
        __syncthreads();
    }
    if (e < 8) {
        float s8 = 0.f;
#pragma unroll
        for (int k = 0; k < 8; k++) s8 += tv[k];
        g_topi[t * CK + e] = ti[e];
        g_topw[t * CK + e] = tv[e] / s8;
    }
}

// ---------------- routing bookkeeping ----------------
__global__ void zero_counts_kernel() { if (threadIdx.x < CE) g_counts[threadIdx.x] = 0; }

__global__ void count_kernel() {
    int i = blockIdx.x * blockDim.x + threadIdx.x;
    if (i < NSLOT) atomicAdd(&g_counts[g_topi[i]], 1);
}

__global__ void scan_kernel() {
    int acc = 0;
    for (int e = 0; e < CE; e++) {
        g_offsets[e] = acc;
        g_cursor[e]  = acc;
        acc += ((g_counts[e] + 127) >> 7) << 7;
    }
}

__global__ void init_slots_kernel() {
    int i = blockIdx.x * blockDim.x + threadIdx.x;
    if (i < PADTOT) g_slot_token[i] = 0;
}

__global__ void fill_kernel() {
    int i = blockIdx.x * blockDim.x + threadIdx.x;
    if (i < NSLOT) {
        int e = g_topi[i];
        int p = atomicAdd(&g_cursor[e], 1);
        g_slot_token[p] = i >> 3;
        g_pos_of[i] = p;
    }
}

// ================= unified MoE bf16 GEMM, BK=32 (2 CTAs/SM; R4-proven) =====
constexpr int SM_MOE = 38400;

template<int MODE>
__global__ __launch_bounds__(256, 2)
void moe_gemm_bf16(const float* __restrict__ W) {
    extern __shared__ char smraw[];
    __nv_bfloat16 (*As)[128][40] = (__nv_bfloat16(*)[128][40])smraw;
    __nv_bfloat16 (*Bs)[32][72]  = (__nv_bfloat16(*)[32][72])(smraw + 20480);
    int* stok = (int*)(smraw + 29696);
    float (*scr)[16][16] = (float(*)[16][16])(smraw + 30208);

    constexpr int KDIM = (MODE == 2) ? CF : CD;
    constexpr int NDIM = (MODE == 2) ? CD : CF;

    int e = blockIdx.y;
    int n0 = blockIdx.x * 64;
    int off = g_offsets[e], cnt = g_counts[e];
    int ntiles = (cnt + 127) >> 7;
    const float* Bm = W + (size_t)e * KDIM * NDIM;

    int tid = threadIdx.x;
    int w = tid >> 5, wm = w & 3, wn = w >> 2;
    int lane = tid & 31;
    int b_row = tid >> 4, b_c4 = (tid & 15) * 4;

    for (int rt = 0; rt < ntiles; rt++) {
        size_t abase = (size_t)(off + rt * 128);
        if (MODE < 2) {
            if (tid < 128) stok[tid] = g_slot_token[abase + tid];
            __syncthreads();
        }

        FragCB acc[2][2];
#pragma unroll
        for (int i = 0; i < 2; i++)
#pragma unroll
            for (int j = 0; j < 2; j++) wmma::fill_fragment(acc[i][j], 0.f);

        uint4 raA[2]; float4 rb[2];
        constexpr int nk = KDIM / 32;
#pragma unroll
        for (int it = 0; it < 2; it++) {
            int i = tid + it * 256;
            int row = i >> 2, c8 = (i & 3) * 8;
            if (MODE < 2)
                raA[it] = *(const uint4*)&g_ht_bf[(size_t)stok[row] * CD + c8];
            else
                raA[it] = *(const uint4*)&g_act_bf[(abase + row) * CF + c8];
        }
#pragma unroll
        for (int it = 0; it < 2; it++)
            rb[it] = *(const float4*)&Bm[(size_t)(b_row + it * 16) * NDIM + n0 + b_c4];
#pragma unroll
        for (int it = 0; it < 2; it++) {
            int i = tid + it * 256;
            int row = i >> 2, c8 = (i & 3) * 8;
            *(uint4*)&As[0][row][c8] = raA[it];
        }
#pragma unroll
        for (int it = 0; it < 2; it++)
            st_bf4(&Bs[0][b_row + it * 16][b_c4], rb[it]);
        __syncthreads();

        for (int k = 0; k < nk; k++) {
            int cur = k & 1;
            if (k + 1 < nk) {
                int k0 = (k + 1) * 32;
#pragma unroll
                for (int it = 0; it < 2; it++) {
                    int i = tid + it * 256;
                    int row = i >> 2, c8 = (i & 3) * 8;
                    if (MODE < 2)
                        raA[it] = *(const uint4*)&g_ht_bf[(size_t)stok[row] * CD + k0 + c8];
                    else
                        raA[it] = *(const uint4*)&g_act_bf[(abase + row) * CF + k0 + c8];
                }
#pragma unroll
                for (int it = 0; it < 2; it++)
                    rb[it] = *(const float4*)&Bm[(size_t)(k0 + b_row + it * 16) * NDIM + n0 + b_c4];
            }
#pragma unroll
            for (int kk = 0; kk < 2; kk++) {
                FragAB a[2]; FragBB b[2];
#pragma unroll
                for (int i = 0; i < 2; i++)
                    wmma::load_matrix_sync(a[i], &As[cur][wm * 32 + i * 16][kk * 16], 40);
#pragma unroll
                for (int j = 0; j < 2; j++)
                    wmma::load_matrix_sync(b[j], &Bs[cur][kk * 16][wn * 32 + j * 16], 72);
#pragma unroll
                for (int i = 0; i < 2; i++)
#pragma unroll
                    for (int j = 0; j < 2; j++) wmma::mma_sync(acc[i][j], a[i], b[j], acc[i][j]);
            }
            if (k + 1 < nk) {
                int nxt = cur ^ 1;
#pragma unroll
                for (int it = 0; it < 2; it++) {
                    int i = tid + it * 256;
                    int row = i >> 2, c8 = (i & 3) * 8;
                    *(uint4*)&As[nxt][row][c8] = raA[it];
                }
#pragma unroll
                for (int it = 0; it < 2; it++)
                    st_bf4(&Bs[nxt][b_row + it * 16][b_c4], rb[it]);
            }
            __syncthreads();
        }

        if (MODE == 0) {
#pragma unroll
            for (int i = 0; i < 2; i++)
#pragma unroll
                for (int j = 0; j < 2; j++) {
                    float* cp = g_gate + (abase + wm * 32 + i * 16) * CF + n0 + wn * 32 + j * 16;
                    wmma::store_matrix_sync(cp, acc[i][j], CF, wmma::mem_row_major);
                }
        } else if (MODE == 2) {
#pragma unroll
            for (int i = 0; i < 2; i++)
#pragma unroll
                for (int j = 0; j < 2; j++) {
                    float* cp = g_y + (abase + wm * 32 + i * 16) * CD + n0 + wn * 32 + j * 16;
                    wmma::store_matrix_sync(cp, acc[i][j], CD, wmma::mem_row_major);
                }
        } else {
#pragma unroll
            for (int i = 0; i < 2; i++)
#pragma unroll
                for (int j = 0; j < 2; j++) {
                    wmma::store_matrix_sync(&scr[w][0][0], acc[i][j], 16, wmma::mem_row_major);
                    __syncwarp();
                    {
                        int r = lane >> 1, cb = (lane & 1) * 8;
                        size_t grow = abase + wm * 32 + i * 16 + r;
                        int col = n0 + wn * 32 + j * 16 + cb;
                        const float* gp = &g_gate[grow * CF + col];
                        float4 g0 = *(const float4*)gp;
                        float4 g1 = *(const float4*)(gp + 4);
                        float4 u0 = *(float4*)&scr[w][r][cb];
                        float4 u1 = *(float4*)&scr[w][r][cb + 4];
                        float4 o0, o1;
                        o0.x = (g0.x / (1.f + expf(-g0.x))) * u0.x;
                        o0.y = (g0.y / (1.f + expf(-g0.y))) * u0.y;
                        o0.z = (g0.z / (1.f + expf(-g0.z))) * u0.z;
                        o0.w = (g0.w / (1.f + expf(-g0.w))) * u0.w;
                        o1.x = (g1.x / (1.f + expf(-g1.x))) * u1.x;
                        o1.y = (g1.y / (1.f + expf(-g1.y))) * u1.y;
                        o1.z = (g1.z / (1.f + expf(-g1.z))) * u1.z;
                        o1.w = (g1.w / (1.f + expf(-g1.w))) * u1.w;
                        __nv_bfloat16* dst = g_act_bf + grow * CF + col;
                        st_bf4(dst, o0);
                        st_bf4(dst + 4, o1);
                    }
                    __syncwarp();
                }
        }
        __syncthreads();
    }
}

// ---------------- final combine ----------------
__global__ void final_add_kernel(float* __restrict__ out) {
    int t = blockIdx.x;
    __shared__ int   pos[8];
    __shared__ float w[8];
    if (threadIdx.x < 8) {
        pos[threadIdx.x] = g_pos_of[t * CK + threadIdx.x];
        w[threadIdx.x]   = g_topw[t * CK + threadIdx.x];
    }
    __syncthreads();
    for (int d = threadIdx.x; d < CD; d += 256) {
        float acc = out[(size_t)t * CD + d];
#pragma unroll
        for (int k = 0; k < 8; k++)
            acc += w[k] * g_y[(size_t)pos[k] * CD + d];
        out[(size_t)t * CD + d] = acc;
    }
}

// ---------------- launch ----------------
extern "C" void kernel_launch(void* const* d_in, const int* in_sizes, int n_in,
                              void* d_out, int out_size) {
    const float* x        = (const float*)d_in[0];
    const float* cos_     = (const float*)d_in[1];
    const float* sin_     = (const float*)d_in[2];
    const float* ln1_w    = (const float*)d_in[3];
    const float* wq       = (const float*)d_in[4];
    const float* wk       = (const float*)d_in[5];
    const float* wv       = (const float*)d_in[6];
    const float* wo       = (const float*)d_in[7];
    const float* qn_w     = (const float*)d_in[8];
    const float* kn_w     = (const float*)d_in[9];
    const float* ln2_w    = (const float*)d_in[10];
    const float* router_w = (const float*)d_in[11];
    const float* w_gate   = (const float*)d_in[12];
    const float* w_up     = (const float*)d_in[13];
    const float* w_down   = (const float*)d_in[14];
    float* out = (float*)d_out;

    cudaFuncSetAttribute(gemm_tf32_pipe,   cudaFuncAttributeMaxDynamicSharedMemorySize, SM_TF32);
    cudaFuncSetAttribute(qkv_tf32,         cudaFuncAttributeMaxDynamicSharedMemorySize, SM_TF32);
    cudaFuncSetAttribute(attn_kernel_mma,  cudaFuncAttributeMaxDynamicSharedMemorySize, SM_ATTN);
    cudaFuncSetAttribute(moe_gemm_bf16<0>, cudaFuncAttributeMaxDynamicSharedMemorySize, SM_MOE);
    cudaFuncSetAttribute(moe_gemm_bf16<1>, cudaFuncAttributeMaxDynamicSharedMemorySize, SM_MOE);
    cudaFuncSetAttribute(moe_gemm_bf16<2>, cudaFuncAttributeMaxDynamicSharedMemorySize, SM_MOE);

    float *p_h, *p_o, *p_ht, *p_logits;
    __nv_bfloat16 *p_ht_bf;
    cudaGetSymbolAddress((void**)&p_h,  g_h);
    cudaGetSymbolAddress((void**)&p_o,  g_o);
    cudaGetSymbolAddress((void**)&p_ht, g_ht);
    cudaGetSymbolAddress((void**)&p_ht_bf, g_ht_bf);
    cudaGetSymbolAddress((void**)&p_logits, g_logits);

    // 1. h = rmsnorm(x)
    rmsnorm_kernel<<<CT, 256>>>(x, ln1_w, p_h);
    // 2. fused q,k,v projections
    qkv_tf32<<<dim3(48, CT / 128), 256, SM_TF32>>>(p_h, wq, wk, wv);
    // 3. per-head q/k rmsnorm + rope
    qknorm_rope_kernel<<<dim3(CT, CH + CKVH), 128>>>(cos_, sin_, qn_w, kn_w);
    // 4. attention (tf32 mma, fp32 softmax)
    attn_kernel_mma<<<dim3(CS / 64, CH, CB), 128, SM_ATTN>>>();
    // 5. out = o @ wo + x
    gemm_tf32_pipe<<<dim3(CD / 64, CT / 128), 256, SM_TF32>>>(p_o, wo, x, out, CD, CD);
    // 6. ht = rmsnorm(out), fp32 + bf16
    rmsnorm_bf_kernel<<<CT, 256>>>(out, ln2_w, p_ht, p_ht_bf);
    // 7. router logits (exact fp32) + top-8
    gemm64<<<dim3(CE / 64, CT / 64), 256>>>(p_ht, router_w, nullptr, p_logits, CT, CE, CD);
    topk_kernel<<<CT, 64>>>();
    // 8. routing bookkeeping
    zero_counts_kernel<<<1, 64>>>();
    count_kernel<<<NSLOT / 256, 256>>>();
    scan_kernel<<<1, 1>>>();
    init_slots_kernel<<<PADTOT / 256, 256>>>();
    fill_kernel<<<NSLOT / 256, 256>>>();
    // 9. MoE: gate, up(+silu), down (bf16 BK=32, 2 CTAs/SM)
    moe_gemm_bf16<0><<<dim3(CF / 64, CE), 256, SM_MOE>>>(w_gate);
    moe_gemm_bf16<1><<<dim3(CF / 64, CE), 256, SM_MOE>>>(w_up);
    moe_gemm_bf16<2><<<dim3(CD / 64, CE), 256, SM_MOE>>>(w_down);
    // 10. deterministic per-token combine
    final_add_kernel<<<CT, 256>>>(out);
}

// round 10
// speedup vs baseline: 3.3468x; 1.0170x over previous
#include <cuda_runtime.h>
#include <cuda_bf16.h>
#include <math.h>
#include <mma.h>
using namespace nvcuda;

// ---------------- problem constants ----------------
constexpr int CB  = 2;
constexpr int CS  = 1024;
constexpr int CD  = 2048;
constexpr int CH  = 16;
constexpr int CKVH= 4;
constexpr int CHD = 128;
constexpr int CE  = 64;
constexpr int CK  = 8;
constexpr int CF  = 768;
constexpr int CT  = CB * CS;             // 2048
constexpr float CEPS = 1e-6f;
constexpr int NSLOT = CT * CK;           // 16384
constexpr int PADTOT = NSLOT + CE * 128; // 24576

// ---------------- scratch ----------------
__device__ float g_h   [CT * CD];
__device__ float g_q   [CT * CH  * CHD];
__device__ float g_k   [CT * CKVH* CHD];
__device__ float g_v   [CT * CKVH* CHD];
__device__ float g_o   [CT * CH  * CHD];
__device__ float g_ht  [CT * CD];
__device__ __nv_bfloat16 g_ht_bf[CT * CD];
__device__ float g_logits[CT * CE];
__device__ int   g_topi[CT * CK];
__device__ float g_topw[CT * CK];
__device__ int   g_counts[CE];
__device__ int   g_offsets[CE];
__device__ int   g_cursor[CE];
__device__ int   g_slot_token[PADTOT];
__device__ int   g_pos_of[NSLOT];
__device__ float g_gate[(size_t)PADTOT * CF];
__device__ __nv_bfloat16 g_act_bf[(size_t)PADTOT * CF];
__device__ float g_y   [(size_t)PADTOT * CD];

// ---------------- helpers ----------------
__device__ __forceinline__ void st_bf4(__nv_bfloat16* p, float4 v) {
    __nv_bfloat162 lo = __floats2bfloat162_rn(v.x, v.y);
    __nv_bfloat162 hi = __floats2bfloat162_rn(v.z, v.w);
    uint2 u;
    u.x = *(unsigned int*)&lo;
    u.y = *(unsigned int*)&hi;
    *(uint2*)p = u;
}

__device__ __forceinline__ unsigned int f2tf32(float x) {
    unsigned int r;
    asm("cvt.rna.tf32.f32 %0, %1;" : "=r"(r) : "f"(x));
    return r;
}
__device__ __forceinline__ float tfr(float x) {         // tf32-round, keep as float
    return __uint_as_float(f2tf32(x));
}
__device__ __forceinline__ float4 tfr4(float4 v) {
    return make_float4(tfr(v.x), tfr(v.y), tfr(v.z), tfr(v.w));
}

__device__ __forceinline__ void mma_tf32(float* c, unsigned int a0, unsigned int a1,
                                         unsigned int a2, unsigned int a3,
                                         unsigned int b0, unsigned int b1) {
    asm volatile(
        "mma.sync.aligned.m16n8k8.row.col.f32.tf32.tf32.f32 "
        "{%0,%1,%2,%3}, {%4,%5,%6,%7}, {%8,%9}, {%0,%1,%2,%3};"
        : "+f"(c[0]), "+f"(c[1]), "+f"(c[2]), "+f"(c[3])
        : "r"(a0), "r"(a1), "r"(a2), "r"(a3), "r"(b0), "r"(b1));
}

// ---------------- rmsnorm ----------------
__global__ void rmsnorm_kernel(const float* __restrict__ in,
                               const float* __restrict__ w,
                               float* __restrict__ out) {
    int t = blockIdx.x;
    const float* row = in + (size_t)t * CD;
    float ss = 0.f;
    for (int d = threadIdx.x; d < CD; d += 256) { float v = row[d]; ss += v * v; }
    __shared__ float red[256];
    red[threadIdx.x] = ss; __syncthreads();
    for (int st = 128; st > 0; st >>= 1) {
        if (threadIdx.x < st) red[threadIdx.x] += red[threadIdx.x + st];
        __syncthreads();
    }
    float scale = rsqrtf(red[0] / (float)CD + CEPS);
    for (int d = threadIdx.x; d < CD; d += 256)
        out[(size_t)t * CD + d] = row[d] * scale * w[d];
}

__global__ void rmsnorm_bf_kernel(const float* __restrict__ in,
                                  const float* __restrict__ w,
                                  float* __restrict__ out,
                                  __nv_bfloat16* __restrict__ outb) {
    int t = blockIdx.x;
    const float* row = in + (size_t)t * CD;
    float ss = 0.f;
    for (int d = threadIdx.x; d < CD; d += 256) { float v = row[d]; ss += v * v; }
    __shared__ float red[256];
    red[threadIdx.x] = ss; __syncthreads();
    for (int st = 128; st > 0; st >>= 1) {
        if (threadIdx.x < st) red[threadIdx.x] += red[threadIdx.x + st];
        __syncthreads();
    }
    float scale = rsqrtf(red[0] / (float)CD + CEPS);
    for (int d = threadIdx.x; d < CD; d += 256) {
        float v = row[d] * scale * w[d];
        out[(size_t)t * CD + d] = v;
        outb[(size_t)t * CD + d] = __float2bfloat16(v);
    }
}

// ---------------- scalar GEMM (router: exact fp32 feeds top-k) -------
__global__ void gemm64(const float* __restrict__ A, const float* __restrict__ Bm,
                       const float* __restrict__ res, float* __restrict__ C,
                       int M, int N, int K) {
    __shared__ float As[16][65];
    __shared__ float Bs[16][64];
    int tid = threadIdx.x;
    int tx = tid & 15, ty = tid >> 4;
    int m0 = blockIdx.y * 64, n0 = blockIdx.x * 64;
    int arow = tid >> 2;
    int acol = (tid & 3) * 4;
    int blin = tid * 4;
    int brow = blin >> 6;
    int bcol = blin & 63;
    const float* Aptr = A + (size_t)(m0 + arow) * K + acol;
    const float* Bptr = Bm + (size_t)brow * N + n0 + bcol;
    float acc[4][4] = {};
    for (int k0 = 0; k0 < K; k0 += 16) {
        float4 av = *(const float4*)(Aptr + k0);
        float4 bv = *(const float4*)(Bptr + (size_t)k0 * N);
        As[acol + 0][arow] = av.x; As[acol + 1][arow] = av.y;
        As[acol + 2][arow] = av.z; As[acol + 3][arow] = av.w;
        *(float4*)&Bs[brow][bcol] = bv;
        __syncthreads();
#pragma unroll
        for (int kk = 0; kk < 16; kk++) {
            float a[4], b[4];
#pragma unroll
            for (int i = 0; i < 4; i++) a[i] = As[kk][ty * 4 + i];
#pragma unroll
            for (int j = 0; j < 4; j++) b[j] = Bs[kk][tx * 4 + j];
#pragma unroll
            for (int i = 0; i < 4; i++)
#pragma unroll
                for (int j = 0; j < 4; j++) acc[i][j] += a[i] * b[j];
        }
        __syncthreads();
    }
#pragma unroll
    for (int i = 0; i < 4; i++)
#pragma unroll
        for (int j = 0; j < 4; j++) {
            size_t idx = (size_t)(m0 + ty * 4 + i) * N + n0 + tx * 4 + j;
            C[idx] = acc[i][j] + (res ? res[idx] : 0.f);
        }
}

// ---------------- fragment types ----------------
using FragAT = wmma::fragment<wmma::matrix_a, 16, 16, 8, wmma::precision::tf32, wmma::row_major>;
using FragBT = wmma::fragment<wmma::matrix_b, 16, 16, 8, wmma::precision::tf32, wmma::row_major>;
using FragAB = wmma::fragment<wmma::matrix_a, 16, 16, 16, __nv_bfloat16, wmma::row_major>;
using FragBB = wmma::fragment<wmma::matrix_b, 16, 16, 16, __nv_bfloat16, wmma::row_major>;
using FragC  = wmma::fragment<wmma::accumulator, 16, 16, 8, float>;
using FragCB = wmma::fragment<wmma::accumulator, 16, 16, 16, float>;

// ================= TF32 dense GEMM body (pre-converted smem) =======
// smem holds tf32-rounded fp32 values; fragment loads need NO conversion.
constexpr int SM_TF32 = 2*128*36*4 + 2*32*68*4;   // 54272

__device__ __forceinline__
void gemm_tf32_body(char* smraw, const float* __restrict__ A, const float* __restrict__ B,
                    const float* __restrict__ res, float* __restrict__ C,
                    int N, int K, int m0, int n0) {
    float (*As)[128][36] = (float(*)[128][36])smraw;
    float (*Bs)[32][68]  = (float(*)[32][68])(smraw + 2*128*36*4);
    int tid = threadIdx.x;
    int w = tid >> 5, wm = w & 3, wn = w >> 2;

    int a_row = tid >> 3, a_c4 = (tid & 7) * 4;
    int b_row = tid >> 4, b_c4 = (tid & 15) * 4;

    FragC acc[2][2];
#pragma unroll
    for (int i = 0; i < 2; i++)
#pragma unroll
        for (int j = 0; j < 2; j++) wmma::fill_fragment(acc[i][j], 0.f);

    float4 ra[4], rb[2];
    int nk = K / 32;
#pragma unroll
    for (int it = 0; it < 4; it++)
        ra[it] = *(const float4*)&A[(size_t)(m0 + a_row + it * 32) * K + a_c4];
#pragma unroll
    for (int it = 0; it < 2; it++)
        rb[it] = *(const float4*)&B[(size_t)(b_row + it * 16) * N + n0 + b_c4];
#pragma unroll
    for (int it = 0; it < 4; it++) *(float4*)&As[0][a_row + it * 32][a_c4] = tfr4(ra[it]);
#pragma unroll
    for (int it = 0; it < 2; it++) *(float4*)&Bs[0][b_row + it * 16][b_c4] = tfr4(rb[it]);
    __syncthreads();

    for (int k = 0; k < nk; k++) {
        int cur = k & 1;
        if (k + 1 < nk) {
            int k0 = (k + 1) * 32;
#pragma unroll
            for (int it = 0; it < 4; it++)
                ra[it] = *(const float4*)&A[(size_t)(m0 + a_row + it * 32) * K + k0 + a_c4];
#pragma unroll
            for (int it = 0; it < 2; it++)
                rb[it] = *(const float4*)&B[(size_t)(k0 + b_row + it * 16) * N + n0 + b_c4];
        }
#pragma unroll
        for (int kk = 0; kk < 4; kk++) {
            FragAT a[2]; FragBT b[2];
#pragma unroll
            for (int i = 0; i < 2; i++)
                wmma::load_matrix_sync(a[i], &As[cur][wm * 32 + i * 16][kk * 8], 36);
#pragma unroll
            for (int j = 0; j < 2; j++)
                wmma::load_matrix_sync(b[j], &Bs[cur][kk * 8][wn * 32 + j * 16], 68);
#pragma unroll
            for (int i = 0; i < 2; i++)
#pragma unroll
                for (int j = 0; j < 2; j++) wmma::mma_sync(acc[i][j], a[i], b[j], acc[i][j]);
        }
        if (k + 1 < nk) {
            int nxt = cur ^ 1;
#pragma unroll
            for (int it = 0; it < 4; it++) *(float4*)&As[nxt][a_row + it * 32][a_c4] = tfr4(ra[it]);
#pragma unroll
            for (int it = 0; it < 2; it++) *(float4*)&Bs[nxt][b_row + it * 16][b_c4] = tfr4(rb[it]);
        }
        __syncthreads();
    }
#pragma unroll
    for (int i = 0; i < 2; i++)
#pragma unroll
        for (int j = 0; j < 2; j++) {
            size_t co = (size_t)(m0 + wm * 32 + i * 16) * N + n0 + wn * 32 + j * 16;
            if (res) {
                FragC r;
                wmma::load_matrix_sync(r, res + co, N, wmma::mem_row_major);
#pragma unroll
                for (int e2 = 0; e2 < r.num_elements; e2++) acc[i][j].x[e2] += r.x[e2];
            }
            wmma::store_matrix_sync(C + co, acc[i][j], N, wmma::mem_row_major);
        }
}

__global__ __launch_bounds__(256, 2)
void gemm_tf32_pipe(const float* __restrict__ A, const float* __restrict__ B,
                    const float* __restrict__ res, float* __restrict__ C,
                    int N, int K) {
    extern __shared__ char smraw[];
    gemm_tf32_body(smraw, A, B, res, C, N, K, blockIdx.y * 128, blockIdx.x * 64);
}

// fused QKV projection: one launch, 48 n-tiles (32 Q + 8 K + 8 V)
__global__ __launch_bounds__(256, 2)
void qkv_tf32(const float* __restrict__ A,
              const float* __restrict__ wq, const float* __restrict__ wk,
              const float* __restrict__ wv) {
    extern __shared__ char smraw[];
    int nt = blockIdx.x;
    const float* B; float* C; int N, n0;
    if (nt < 32)      { B = wq; C = g_q; N = CH  * CHD; n0 = nt * 64; }
    else if (nt < 40) { B = wk; C = g_k; N = CKVH* CHD; n0 = (nt - 32) * 64; }
    else              { B = wv; C = g_v; N = CKVH* CHD; n0 = (nt - 40) * 64; }
    gemm_tf32_body(smraw, A, B, nullptr, C, N, CD, blockIdx.y * 128, n0);
}

// ---------------- per-head q/k rmsnorm + rope ----------------
__global__ void qknorm_rope_kernel(const float* __restrict__ cos_,
                                   const float* __restrict__ sin_,
                                   const float* __restrict__ qn_w,
                                   const float* __restrict__ kn_w) {
    int t = blockIdx.x;
    int hy = blockIdx.y;
    int d = threadIdx.x;
    float* ptr; const float* w;
    if (hy < CH) { ptr = g_q + ((size_t)t * CH + hy) * CHD;          w = qn_w; }
    else         { ptr = g_k + ((size_t)t * CKVH + (hy - CH)) * CHD; w = kn_w; }
    float v = ptr[d];
    float ss = v * v;
#pragma unroll
    for (int off = 16; off > 0; off >>= 1) ss += __shfl_xor_sync(0xffffffffu, ss, off);
    __shared__ float ws[4];
    if ((d & 31) == 0) ws[d >> 5] = ss;
    __syncthreads();
    float tot = ws[0] + ws[1] + ws[2] + ws[3];
    float nrm = v * rsqrtf(tot / (float)CHD + CEPS) * w[d];
    __shared__ float nbuf[128];
    nbuf[d] = nrm;
    __syncthreads();
    float rot = (d < 64) ? -nbuf[d + 64] : nbuf[d - 64];
    float c = cos_[(size_t)t * CHD + d];
    float s = sin_[(size_t)t * CHD + d];
    ptr[d] = nrm * c + rot * s;
}

// ================= flash attention v3.1: tf32 mma, pre-converted smem ====
// smem: Qs[64][132] | KVs[32][132] | Ss[64][36]  (tf32-rounded fp32)
constexpr int SM_ATTN = (64*132 + 32*132 + 64*36) * 4;   // 59904

__global__ void attn_kernel_mma() {
    extern __shared__ char sm[];
    float (*Qs)[132] = (float(*)[132])sm;
    float (*KVs)[132] = (float(*)[132])(sm + 64*132*4);
    float (*Ss)[36]  = (float(*)[36])(sm + (64+32)*132*4);

    int qt = blockIdx.x;
    int h  = blockIdx.y;
    int b  = blockIdx.z;
    int kvh = h / (CH / CKVH);
    int tid = threadIdx.x;
    int w = tid >> 5, lane = tid & 31;
    int gi = lane >> 2;        // 0..7
    int li = lane & 3;         // 0..3

    // load Q tile (64 x 128), tf32-rounded
    for (int i = tid; i < 64 * 32; i += 128) {
        int rr = i >> 5, c4 = (i & 31) * 4;
        *(float4*)&Qs[rr][c4] = tfr4(
            *(const float4*)&g_q[((size_t)(b * CS + qt * 64 + rr) * CH + h) * CHD + c4]);
    }

    float o[64];
#pragma unroll
    for (int i = 0; i < 64; i++) o[i] = 0.f;
    float m0 = -1e30f, m1 = -1e30f, l0 = 0.f, l1 = 0.f;
    const float scale = 0.088388347648318447f;   // 1/sqrt(128)
    int r0g = qt * 64 + w * 16 + gi;
    int r1g = r0g + 8;

    int jmax = 2 * qt + 1;
    for (int jt = 0; jt <= jmax; jt++) {
        __syncthreads();
        for (int i = tid; i < 32 * 32; i += 128) {
            int rr = i >> 5, c4 = (i & 31) * 4;
            *(float4*)&KVs[rr][c4] = tfr4(
                *(const float4*)&g_k[((size_t)(b * CS + jt * 32 + rr) * CKVH + kvh) * CHD + c4]);
        }
        __syncthreads();

        // S_w(16x32) = Q_w(16x128) @ K^T   (operands pre-rounded; plain loads)
        float sacc[4][4];
#pragma unroll
        for (int n = 0; n < 4; n++)
#pragma unroll
            for (int i = 0; i < 4; i++) sacc[n][i] = 0.f;
#pragma unroll
        for (int k8 = 0; k8 < 16; k8++) {
            unsigned int a0 = __float_as_uint(Qs[w * 16 + gi][k8 * 8 + li]);
            unsigned int a1 = __float_as_uint(Qs[w * 16 + gi + 8][k8 * 8 + li]);
            unsigned int a2 = __float_as_uint(Qs[w * 16 + gi][k8 * 8 + li + 4]);
            unsigned int a3 = __float_as_uint(Qs[w * 16 + gi + 8][k8 * 8 + li + 4]);
#pragma unroll
            for (int n = 0; n < 4; n++) {
                unsigned int b0 = __float_as_uint(KVs[n * 8 + gi][k8 * 8 + li]);
                unsigned int b1 = __float_as_uint(KVs[n * 8 + gi][k8 * 8 + li + 4]);
                mma_tf32(sacc[n], a0, a1, a2, a3, b0, b1);
            }
        }

        // scale + causal mask + online softmax
        float lm0 = -1e30f, lm1 = -1e30f;
#pragma unroll
        for (int n = 0; n < 4; n++) {
            int c0 = jt * 32 + n * 8 + 2 * li;
#pragma unroll
            for (int i = 0; i < 2; i++) {
                float v0 = sacc[n][i] * scale;
                float v1 = sacc[n][i + 2] * scale;
                if (c0 + i > r0g) v0 = -1e30f;
                if (c0 + i > r1g) v1 = -1e30f;
                sacc[n][i] = v0; sacc[n][i + 2] = v1;
                lm0 = fmaxf(lm0, v0); lm1 = fmaxf(lm1, v1);
            }
        }
        lm0 = fmaxf(lm0, __shfl_xor_sync(0xffffffffu, lm0, 1));
        lm0 = fmaxf(lm0, __shfl_xor_sync(0xffffffffu, lm0, 2));
        lm1 = fmaxf(lm1, __shfl_xor_sync(0xffffffffu, lm1, 1));
        lm1 = fmaxf(lm1, __shfl_xor_sync(0xffffffffu, lm1, 2));
        float tm0 = fmaxf(m0, lm0), tm1 = fmaxf(m1, lm1);
        float al0 = expf(m0 - tm0), al1 = expf(m1 - tm1);
        float ls0 = 0.f, ls1 = 0.f;
#pragma unroll
        for (int n = 0; n < 4; n++) {
#pragma unroll
            for (int i = 0; i < 2; i++) {
                float p0 = expf(sacc[n][i] - tm0);
                float p1 = expf(sacc[n][i + 2] - tm1);
                sacc[n][i] = p0; sacc[n][i + 2] = p1;
                ls0 += p0; ls1 += p1;
            }
        }
        ls0 += __shfl_xor_sync(0xffffffffu, ls0, 1);
        ls0 += __shfl_xor_sync(0xffffffffu, ls0, 2);
        ls1 += __shfl_xor_sync(0xffffffffu, ls1, 1);
        ls1 += __shfl_xor_sync(0xffffffffu, ls1, 2);
        l0 = l0 * al0 + ls0;
        l1 = l1 * al1 + ls1;
        m0 = tm0; m1 = tm1;

        // stash P to smem, tf32-rounded (l sums above used exact fp32 p)
#pragma unroll
        for (int n = 0; n < 4; n++) {
            Ss[w * 16 + gi][n * 8 + 2 * li]         = tfr(sacc[n][0]);
            Ss[w * 16 + gi][n * 8 + 2 * li + 1]     = tfr(sacc[n][1]);
            Ss[w * 16 + gi + 8][n * 8 + 2 * li]     = tfr(sacc[n][2]);
            Ss[w * 16 + gi + 8][n * 8 + 2 * li + 1] = tfr(sacc[n][3]);
        }

        // rescale O accumulators
#pragma unroll
        for (int n = 0; n < 16; n++) {
            o[n * 4 + 0] *= al0; o[n * 4 + 1] *= al0;
            o[n * 4 + 2] *= al1; o[n * 4 + 3] *= al1;
        }

        __syncthreads();   // all warps done reading K
        for (int i = tid; i < 32 * 32; i += 128) {
            int rr = i >> 5, c4 = (i & 31) * 4;
            *(float4*)&KVs[rr][c4] = tfr4(
                *(const float4*)&g_v[((size_t)(b * CS + jt * 32 + rr) * CKVH + kvh) * CHD + c4]);
        }
        __syncwarp();
        __syncthreads();   // V ready

        // O_w(16x128) += P_w(16x32) @ V(32x128)
#pragma unroll
        for (int k8 = 0; k8 < 4; k8++) {
            unsigned int a0 = __float_as_uint(Ss[w * 16 + gi][k8 * 8 + li]);
            unsigned int a1 = __float_as_uint(Ss[w * 16 + gi + 8][k8 * 8 + li]);
            unsigned int a2 = __float_as_uint(Ss[w * 16 + gi][k8 * 8 + li + 4]);
            unsigned int a3 = __float_as_uint(Ss[w * 16 + gi + 8][k8 * 8 + li + 4]);
#pragma unroll
            for (int n = 0; n < 16; n++) {
                unsigned int b0 = __float_as_uint(KVs[k8 * 8 + li][n * 8 + gi]);
                unsigned int b1 = __float_as_uint(KVs[k8 * 8 + li + 4][n * 8 + gi]);
                mma_tf32(&o[n * 4], a0, a1, a2, a3, b0, b1);
            }
        }
    }

    // epilogue
    float inv0 = 1.f / l0, inv1 = 1.f / l1;
    int t0 = b * CS + r0g, t1 = b * CS + r1g;
    float* op0 = &g_o[((size_t)t0 * CH + h) * CHD];
    float* op1 = &g_o[((size_t)t1 * CH + h) * CHD];
#pragma unroll
    for (int n = 0; n < 16; n++) {
        int col = n * 8 + 2 * li;
        float2 v0 = make_float2(o[n * 4 + 0] * inv0, o[n * 4 + 1] * inv0);
        float2 v1 = make_float2(o[n * 4 + 2] * inv1, o[n * 4 + 3] * inv1);
        *(float2*)&op0[col] = v0;
        *(float2*)&op1[col] = v1;
    }
}

// ---------------- router softmax + top-8 ----------------
__global__ void topk_kernel() {
    int t = blockIdx.x, e = threadIdx.x;
    __shared__ float red[64];
    __shared__ int   redi[64];
    __shared__ float tv[8];
    __shared__ int   ti[8];
    float lg = g_logits[t * CE + e];
    red[e] = lg; __syncthreads();
    for (int st = 32; st > 0; st >>= 1) {
        if (e < st) red[e] = fmaxf(red[e], red[e + st]);
        __syncthreads();
    }
    float mx = red[0]; __syncthreads();
    float ex = expf(lg - mx);
    red[e] = ex; __syncthreads();
    for (int st = 32; st > 0; st >>= 1) {
        if (e < st) red[e] += red[e + st];
        __syncthreads();
    }
    float sum = red[0]; __syncthreads();
    float sel = ex / sum;
    for (int k = 0; k < 8; k++) {
        red[e] = sel; redi[e] = e; __syncthreads();
        for (int st = 32; st > 0; st >>= 1) {
            if (e < st) {
                if (red[e + st] > red[e]) { red[e] = red[e + st]; redi[e] = redi[e + st]; }
            }
            __syncthreads();
        }
        if (e == 0) { tv[k] = red[0]; ti[k] = redi[0]; }
        __syncthreads();
        if (e == ti[k]) sel = -1.f;
        __syncthreads();
    }
    if (e < 8) {
        float s8 = 0.f;
#pragma unroll
        for (int k = 0; k < 8; k++) s8 += tv[k];
        g_topi[t * CK + e] = ti[e];
        g_topw[t * CK + e] = tv[e] / s8;
    }
}

// ---------------- routing bookkeeping ----------------
__global__ void zero_counts_kernel() { if (threadIdx.x < CE) g_counts[threadIdx.x] = 0; }

__global__ void count_kernel() {
    int i = blockIdx.x * blockDim.x + threadIdx.x;
    if (i < NSLOT) atomicAdd(&g_counts[g_topi[i]], 1);
}

__global__ void scan_kernel() {
    int acc = 0;
    for (int e = 0; e < CE; e++) {
        g_offsets[e] = acc;
        g_cursor[e]  = acc;
        acc += ((g_counts[e] + 127) >> 7) << 7;
    }
}

__global__ void init_slots_kernel() {
    int i = blockIdx.x * blockDim.x + threadIdx.x;
    if (i < PADTOT) g_slot_token[i] = 0;
}

__global__ void fill_kernel() {
    int i = blockIdx.x * blockDim.x + threadIdx.x;
    if (i < NSLOT) {
        int e = g_topi[i];
        int p = atomicAdd(&g_cursor[e], 1);
        g_slot_token[p] = i >> 3;
        g_pos_of[i] = p;
    }
}

// ================= unified MoE bf16 GEMM, BK=32 (2 CTAs/SM) =====
constexpr int SM_MOE = 38400;

template<int MODE>
__global__ __launch_bounds__(256, 2)
void moe_gemm_bf16(const float* __restrict__ W) {
    extern __shared__ char smraw[];
    __nv_bfloat16 (*As)[128][40] = (__nv_bfloat16(*)[128][40])smraw;
    __nv_bfloat16 (*Bs)[32][72]  = (__nv_bfloat16(*)[32][72])(smraw + 20480);
    int* stok = (int*)(smraw + 29696);
    float (*scr)[16][16] = (float(*)[16][16])(smraw + 30208);

    constexpr int KDIM = (MODE == 2) ? CF : CD;
    constexpr int NDIM = (MODE == 2) ? CD : CF;

    int e = blockIdx.y;
    int n0 = blockIdx.x * 64;
    int off = g_offsets[e], cnt = g_counts[e];
    int ntiles = (cnt + 127) >> 7;
    const float* Bm = W + (size_t)e * KDIM * NDIM;

    int tid = threadIdx.x;
    int w = tid >> 5, wm = w & 3, wn = w >> 2;
    int lane = tid & 31;
    int b_row = tid >> 4, b_c4 = (tid & 15) * 4;

    for (int rt = 0; rt < ntiles; rt++) {
        size_t abase = (size_t)(off + rt * 128);
        if (MODE < 2) {
            if (tid < 128) stok[tid] = g_slot_token[abase + tid];
            __syncthreads();
        }

        FragCB acc[2][2];
#pragma unroll
        for (int i = 0; i < 2; i++)
#pragma unroll
            for (int j = 0; j < 2; j++) wmma::fill_fragment(acc[i][j], 0.f);

        uint4 raA[2]; float4 rb[2];
        constexpr int nk = KDIM / 32;
#pragma unroll
        for (int it = 0; it < 2; it++) {
            int i = tid + it * 256;
            int row = i >> 2, c8 = (i & 3) * 8;
            if (MODE < 2)
                raA[it] = *(const uint4*)&g_ht_bf[(size_t)stok[row] * CD + c8];
            else
                raA[it] = *(const uint4*)&g_act_bf[(abase + row) * CF + c8];
        }
#pragma unroll
        for (int it = 0; it < 2; it++)
            rb[it] = *(const float4*)&Bm[(size_t)(b_row + it * 16) * NDIM + n0 + b_c4];
#pragma unroll
        for (int it = 0; it < 2; it++) {
            int i = tid + it * 256;
            int row = i >> 2, c8 = (i & 3) * 8;
            *(uint4*)&As[0][row][c8] = raA[it];
        }
#pragma unroll
        for (int it = 0; it < 2; it++)
            st_bf4(&Bs[0][b_row + it * 16][b_c4], rb[it]);
        __syncthreads();

        for (int k = 0; k < nk; k++) {
            int cur = k & 1;
            if (k + 1 < nk) {
                int k0 = (k + 1) * 32;
#pragma unroll
                for (int it = 0; it < 2; it++) {
                    int i = tid + it * 256;
                    int row = i >> 2, c8 = (i & 3) * 8;
                    if (MODE < 2)
                        raA[it] = *(const uint4*)&g_ht_bf[(size_t)stok[row] * CD + k0 + c8];
                    else
                        raA[it] = *(const uint4*)&g_act_bf[(abase + row) * CF + k0 + c8];
                }
#pragma unroll
                for (int it = 0; it < 2; it++)
                    rb[it] = *(const float4*)&Bm[(size_t)(k0 + b_row + it * 16) * NDIM + n0 + b_c4];
            }
#pragma unroll
            for (int kk = 0; kk < 2; kk++) {
                FragAB a[2]; FragBB b[2];
#pragma unroll
                for (int i = 0; i < 2; i++)
                    wmma::load_matrix_sync(a[i], &As[cur][wm * 32 + i * 16][kk * 16], 40);
#pragma unroll
                for (int j = 0; j < 2; j++)
                    wmma::load_matrix_sync(b[j], &Bs[cur][kk * 16][wn * 32 + j * 16], 72);
#pragma unroll
                for (int i = 0; i < 2; i++)
#pragma unroll
                    for (int j = 0; j < 2; j++) wmma::mma_sync(acc[i][j], a[i], b[j], acc[i][j]);
            }
            if (k + 1 < nk) {
                int nxt = cur ^ 1;
#pragma unroll
                for (int it = 0; it < 2; it++) {
                    int i = tid + it * 256;
                    int row = i >> 2, c8 = (i & 3) * 8;
                    *(uint4*)&As[nxt][row][c8] = raA[it];
                }
#pragma unroll
                for (int it = 0; it < 2; it++)
                    st_bf4(&Bs[nxt][b_row + it * 16][b_c4], rb[it]);
            }
            __syncthreads();
        }

        if (MODE == 0) {
#pragma unroll
            for (int i = 0; i < 2; i++)
#pragma unroll
                for (int j = 0; j < 2; j++) {
                    float* cp = g_gate + (abase + wm * 32 + i * 16) * CF + n0 + wn * 32 + j * 16;
                    wmma::store_matrix_sync(cp, acc[i][j], CF, wmma::mem_row_major);
                }
        } else if (MODE == 2) {
#pragma unroll
            for (int i = 0; i < 2; i++)
#pragma unroll
                for (int j = 0; j < 2; j++) {
                    float* cp = g_y + (abase + wm * 32 + i * 16) * CD + n0 + wn * 32 + j * 16;
                    wmma::store_matrix_sync(cp, acc[i][j], CD, wmma::mem_row_major);
                }
        } else {
#pragma unroll
            for (int i = 0; i < 2; i++)
#pragma unroll
                for (int j = 0; j < 2; j++) {
                    wmma::store_matrix_sync(&scr[w][0][0], acc[i][j], 16, wmma::mem_row_major);
                    __syncwarp();
                    {
                        int r = lane >> 1, cb = (lane & 1) * 8;
                        size_t grow = abase + wm * 32 + i * 16 + r;
                        int col = n0 + wn * 32 + j * 16 + cb;
                        const float* gp = &g_gate[grow * CF + col];
                        float4 g0 = *(const float4*)gp;
                        float4 g1 = *(const float4*)(gp + 4);
                        float4 u0 = *(float4*)&scr[w][r][cb];
                        float4 u1 = *(float4*)&scr[w][r][cb + 4];
                        float4 o0, o1;
                        o0.x = (g0.x / (1.f + expf(-g0.x))) * u0.x;
                        o0.y = (g0.y / (1.f + expf(-g0.y))) * u0.y;
                        o0.z = (g0.z / (1.f + expf(-g0.z))) * u0.z;
                        o0.w = (g0.w / (1.f + expf(-g0.w))) * u0.w;
                        o1.x = (g1.x / (1.f + expf(-g1.x))) * u1.x;
                        o1.y = (g1.y / (1.f + expf(-g1.y))) * u1.y;
                        o1.z = (g1.z / (1.f + expf(-g1.z))) * u1.z;
                        o1.w = (g1.w / (1.f + expf(-g1.w))) * u1.w;
                        __nv_bfloat16* dst = g_act_bf + grow * CF + col;
                        st_bf4(dst, o0);
                        st_bf4(dst + 4, o1);
                    }
                    __syncwarp();
                }
        }
        __syncthreads();
    }
}

// ---------------- final combine ----------------
__global__ void final_add_kernel(float* __restrict__ out) {
    int t = blockIdx.x;
    __shared__ int   pos[8];
    __shared__ float w[8];
    if (threadIdx.x < 8) {
        pos[threadIdx.x] = g_pos_of[t * CK + threadIdx.x];
        w[threadIdx.x]   = g_topw[t * CK + threadIdx.x];
    }
    __syncthreads();
    for (int d = threadIdx.x; d < CD; d += 256) {
        float acc = out[(size_t)t * CD + d];
#pragma unroll
        for (int k = 0; k < 8; k++)
            acc += w[k] * g_y[(size_t)pos[k] * CD + d];
        out[(size_t)t * CD + d] = acc;
    }
}

// ---------------- launch ----------------
extern "C" void kernel_launch(void* const* d_in, const int* in_sizes, int n_in,
                              void* d_out, int out_size) {
    const float* x        = (const float*)d_in[0];
    const float* cos_     = (const float*)d_in[1];
    const float* sin_     = (const float*)d_in[2];
    const float* ln1_w    = (const float*)d_in[3];
    const float* wq       = (const float*)d_in[4];
    const float* wk       = (const float*)d_in[5];
    const float* wv       = (const float*)d_in[6];
    const float* wo       = (const float*)d_in[7];
    const float* qn_w     = (const float*)d_in[8];
    const float* kn_w     = (const float*)d_in[9];
    const float* ln2_w    = (const float*)d_in[10];
    const float* router_w = (const float*)d_in[11];
    const float* w_gate   = (const float*)d_in[12];
    const float* w_up     = (const float*)d_in[13];
    const float* w_down   = (const float*)d_in[14];
    float* out = (float*)d_out;

    cudaFuncSetAttribute(gemm_tf32_pipe,   cudaFuncAttributeMaxDynamicSharedMemorySize, SM_TF32);
    cudaFuncSetAttribute(qkv_tf32,         cudaFuncAttributeMaxDynamicSharedMemorySize, SM_TF32);
    cudaFuncSetAttribute(attn_kernel_mma,  cudaFuncAttributeMaxDynamicSharedMemorySize, SM_ATTN);
    cudaFuncSetAttribute(moe_gemm_bf16<0>, cudaFuncAttributeMaxDynamicSharedMemorySize, SM_MOE);
    cudaFuncSetAttribute(moe_gemm_bf16<1>, cudaFuncAttributeMaxDynamicSharedMemorySize, SM_MOE);
    cudaFuncSetAttribute(moe_gemm_bf16<2>, cudaFuncAttributeMaxDynamicSharedMemorySize, SM_MOE);

    float *p_h, *p_o, *p_ht, *p_logits;
    __nv_bfloat16 *p_ht_bf;
    cudaGetSymbolAddress((void**)&p_h,  g_h);
    cudaGetSymbolAddress((void**)&p_o,  g_o);
    cudaGetSymbolAddress((void**)&p_ht, g_ht);
    cudaGetSymbolAddress((void**)&p_ht_bf, g_ht_bf);
    cudaGetSymbolAddress((void**)&p_logits, g_logits);

    // 1. h = rmsnorm(x)
    rmsnorm_kernel<<<CT, 256>>>(x, ln1_w, p_h);
    // 2. fused q,k,v projections
    qkv_tf32<<<dim3(48, CT / 128), 256, SM_TF32>>>(p_h, wq, wk, wv);
    // 3. per-head q/k rmsnorm + rope
    qknorm_rope_kernel<<<dim3(CT, CH + CKVH), 128>>>(cos_, sin_, qn_w, kn_w);
    // 4. attention (tf32 mma, fp32 softmax, pre-converted operands)
    attn_kernel_mma<<<dim3(CS / 64, CH, CB), 128, SM_ATTN>>>();
    // 5. out = o @ wo + x
    gemm_tf32_pipe<<<dim3(CD / 64, CT / 128), 256, SM_TF32>>>(p_o, wo, x, out, CD, CD);
    // 6. ht = rmsnorm(out), fp32 + bf16
    rmsnorm_bf_kernel<<<CT, 256>>>(out, ln2_w, p_ht, p_ht_bf);
    // 7. router logits (exact fp32) + top-8
    gemm64<<<dim3(CE / 64, CT / 64), 256>>>(p_ht, router_w, nullptr, p_logits, CT, CE, CD);
    topk_kernel<<<CT, 64>>>();
    // 8. routing bookkeeping
    zero_counts_kernel<<<1, 64>>>();
    count_kernel<<<NSLOT / 256, 256>>>();
    scan_kernel<<<1, 1>>>();
    init_slots_kernel<<<PADTOT / 256, 256>>>();
    fill_kernel<<<NSLOT / 256, 256>>>();
    // 9. MoE: gate, up(+silu), down (bf16 BK=32, 2 CTAs/SM)
    moe_gemm_bf16<0><<<dim3(CF / 64, CE), 256, SM_MOE>>>(w_gate);
    moe_gemm_bf16<1><<<dim3(CF / 64, CE), 256, SM_MOE>>>(w_up);
    moe_gemm_bf16<2><<<dim3(CD / 64, CE), 256, SM_MOE>>>(w_down);
    // 10. deterministic per-token combine
    final_add_kernel<<<CT, 256>>>(out);
}

// round 12
// speedup vs baseline: 3.8915x; 1.1627x over previous
#include <cuda_runtime.h>
#include <cuda_bf16.h>
#include <math.h>
#include <mma.h>
using namespace nvcuda;

// ---------------- problem constants ----------------
constexpr int CB  = 2;
constexpr int CS  = 1024;
constexpr int CD  = 2048;
constexpr int CH  = 16;
constexpr int CKVH= 4;
constexpr int CHD = 128;
constexpr int CE  = 64;
constexpr int CK  = 8;
constexpr int CF  = 768;
constexpr int CT  = CB * CS;             // 2048
constexpr float CEPS = 1e-6f;
constexpr int NSLOT = CT * CK;           // 16384
constexpr int PADTOT = NSLOT + CE * 128; // 24576

// ---------------- scratch ----------------
__device__ float g_h   [CT * CD];
__device__ float g_q   [CT * CH  * CHD];
__device__ float g_k   [CT * CKVH* CHD];
__device__ float g_v   [CT * CKVH* CHD];
__device__ float g_o   [CT * CH  * CHD];
__device__ float g_ht  [CT * CD];
__device__ __nv_bfloat16 g_ht_bf[CT * CD];
__device__ float g_logits[CT * CE];
__device__ int   g_topi[CT * CK];
__device__ float g_topw[CT * CK];
__device__ int   g_counts[CE];
__device__ int   g_offsets[CE];
__device__ int   g_cursor[CE];
__device__ int   g_slot_token[PADTOT];
__device__ int   g_pos_of[NSLOT];
__device__ float g_gate[(size_t)PADTOT * CF];
__device__ __nv_bfloat16 g_act_bf[(size_t)PADTOT * CF];
__device__ float g_y   [(size_t)PADTOT * CD];

// ---------------- helpers ----------------
__device__ __forceinline__ void st_bf4(__nv_bfloat16* p, float4 v) {
    __nv_bfloat162 lo = __floats2bfloat162_rn(v.x, v.y);
    __nv_bfloat162 hi = __floats2bfloat162_rn(v.z, v.w);
    uint2 u;
    u.x = *(unsigned int*)&lo;
    u.y = *(unsigned int*)&hi;
    *(uint2*)p = u;
}

__device__ __forceinline__ unsigned int f2tf32(float x) {
    unsigned int r;
    asm("cvt.rna.tf32.f32 %0, %1;" : "=r"(r) : "f"(x));
    return r;
}
__device__ __forceinline__ float tfr(float x) {
    return __uint_as_float(f2tf32(x));
}
__device__ __forceinline__ float4 tfr4(float4 v) {
    return make_float4(tfr(v.x), tfr(v.y), tfr(v.z), tfr(v.w));
}

__device__ __forceinline__ void mma_tf32(float* c, unsigned int a0, unsigned int a1,
                                         unsigned int a2, unsigned int a3,
                                         unsigned int b0, unsigned int b1) {
    asm volatile(
        "mma.sync.aligned.m16n8k8.row.col.f32.tf32.tf32.f32 "
        "{%0,%1,%2,%3}, {%4,%5,%6,%7}, {%8,%9}, {%0,%1,%2,%3};"
        : "+f"(c[0]), "+f"(c[1]), "+f"(c[2]), "+f"(c[3])
        : "r"(a0), "r"(a1), "r"(a2), "r"(a3), "r"(b0), "r"(b1));
}

// ---------------- rmsnorm ----------------
__global__ void rmsnorm_kernel(const float* __restrict__ in,
                               const float* __restrict__ w,
                               float* __restrict__ out) {
    int t = blockIdx.x;
    const float* row = in + (size_t)t * CD;
    float ss = 0.f;
    for (int d = threadIdx.x; d < CD; d += 256) { float v = row[d]; ss += v * v; }
    __shared__ float red[256];
    red[threadIdx.x] = ss; __syncthreads();
    for (int st = 128; st > 0; st >>= 1) {
        if (threadIdx.x < st) red[threadIdx.x] += red[threadIdx.x + st];
        __syncthreads();
    }
    float scale = rsqrtf(red[0] / (float)CD + CEPS);
    for (int d = threadIdx.x; d < CD; d += 256)
        out[(size_t)t * CD + d] = row[d] * scale * w[d];
}

__global__ void rmsnorm_bf_kernel(const float* __restrict__ in,
                                  const float* __restrict__ w,
                                  float* __restrict__ out,
                                  __nv_bfloat16* __restrict__ outb) {
    int t = blockIdx.x;
    const float* row = in + (size_t)t * CD;
    float ss = 0.f;
    for (int d = threadIdx.x; d < CD; d += 256) { float v = row[d]; ss += v * v; }
    __shared__ float red[256];
    red[threadIdx.x] = ss; __syncthreads();
    for (int st = 128; st > 0; st >>= 1) {
        if (threadIdx.x < st) red[threadIdx.x] += red[threadIdx.x + st];
        __syncthreads();
    }
    float scale = rsqrtf(red[0] / (float)CD + CEPS);
    for (int d = threadIdx.x; d < CD; d += 256) {
        float v = row[d] * scale * w[d];
        out[(size_t)t * CD + d] = v;
        outb[(size_t)t * CD + d] = __float2bfloat16(v);
    }
}

// ---------------- scalar GEMM (router: exact fp32 feeds top-k) -------
__global__ void gemm64(const float* __restrict__ A, const float* __restrict__ Bm,
                       const float* __restrict__ res, float* __restrict__ C,
                       int M, int N, int K) {
    __shared__ float As[16][65];
    __shared__ float Bs[16][64];
    int tid = threadIdx.x;
    int tx = tid & 15, ty = tid >> 4;
    int m0 = blockIdx.y * 64, n0 = blockIdx.x * 64;
    int arow = tid >> 2;
    int acol = (tid & 3) * 4;
    int blin = tid * 4;
    int brow = blin >> 6;
    int bcol = blin & 63;
    const float* Aptr = A + (size_t)(m0 + arow) * K + acol;
    const float* Bptr = Bm + (size_t)brow * N + n0 + bcol;
    float acc[4][4] = {};
    for (int k0 = 0; k0 < K; k0 += 16) {
        float4 av = *(const float4*)(Aptr + k0);
        float4 bv = *(const float4*)(Bptr + (size_t)k0 * N);
        As[acol + 0][arow] = av.x; As[acol + 1][arow] = av.y;
        As[acol + 2][arow] = av.z; As[acol + 3][arow] = av.w;
        *(float4*)&Bs[brow][bcol] = bv;
        __syncthreads();
#pragma unroll
        for (int kk = 0; kk < 16; kk++) {
            float a[4], b[4];
#pragma unroll
            for (int i = 0; i < 4; i++) a[i] = As[kk][ty * 4 + i];
#pragma unroll
            for (int j = 0; j < 4; j++) b[j] = Bs[kk][tx * 4 + j];
#pragma unroll
            for (int i = 0; i < 4; i++)
#pragma unroll
                for (int j = 0; j < 4; j++) acc[i][j] += a[i] * b[j];
        }
        __syncthreads();
    }
#pragma unroll
    for (int i = 0; i < 4; i++)
#pragma unroll
        for (int j = 0; j < 4; j++) {
            size_t idx = (size_t)(m0 + ty * 4 + i) * N + n0 + tx * 4 + j;
            C[idx] = acc[i][j] + (res ? res[idx] : 0.f);
        }
}

// ---------------- fragment types ----------------
using FragAT = wmma::fragment<wmma::matrix_a, 16, 16, 8, wmma::precision::tf32, wmma::row_major>;
using FragBT = wmma::fragment<wmma::matrix_b, 16, 16, 8, wmma::precision::tf32, wmma::row_major>;
using FragAB = wmma::fragment<wmma::matrix_a, 16, 16, 16, __nv_bfloat16, wmma::row_major>;
using FragBB = wmma::fragment<wmma::matrix_b, 16, 16, 16, __nv_bfloat16, wmma::row_major>;
using FragC  = wmma::fragment<wmma::accumulator, 16, 16, 8, float>;
using FragCB = wmma::fragment<wmma::accumulator, 16, 16, 16, float>;

// ================= TF32 dense GEMM body (pre-converted smem) =======
constexpr int SM_TF32 = 2*128*36*4 + 2*32*68*4;   // 54272

__device__ __forceinline__
void gemm_tf32_body(char* smraw, const float* __restrict__ A, const float* __restrict__ B,
                    const float* __restrict__ res, float* __restrict__ C,
                    int N, int K, int m0, int n0) {
    float (*As)[128][36] = (float(*)[128][36])smraw;
    float (*Bs)[32][68]  = (float(*)[32][68])(smraw + 2*128*36*4);
    int tid = threadIdx.x;
    int w = tid >> 5, wm = w & 3, wn = w >> 2;

    int a_row = tid >> 3, a_c4 = (tid & 7) * 4;
    int b_row = tid >> 4, b_c4 = (tid & 15) * 4;

    FragC acc[2][2];
#pragma unroll
    for (int i = 0; i < 2; i++)
#pragma unroll
        for (int j = 0; j < 2; j++) wmma::fill_fragment(acc[i][j], 0.f);

    float4 ra[4], rb[2];
    int nk = K / 32;
#pragma unroll
    for (int it = 0; it < 4; it++)
        ra[it] = *(const float4*)&A[(size_t)(m0 + a_row + it * 32) * K + a_c4];
#pragma unroll
    for (int it = 0; it < 2; it++)
        rb[it] = *(const float4*)&B[(size_t)(b_row + it * 16) * N + n0 + b_c4];
#pragma unroll
    for (int it = 0; it < 4; it++) *(float4*)&As[0][a_row + it * 32][a_c4] = tfr4(ra[it]);
#pragma unroll
    for (int it = 0; it < 2; it++) *(float4*)&Bs[0][b_row + it * 16][b_c4] = tfr4(rb[it]);
    __syncthreads();

    for (int k = 0; k < nk; k++) {
        int cur = k & 1;
        if (k + 1 < nk) {
            int k0 = (k + 1) * 32;
#pragma unroll
            for (int it = 0; it < 4; it++)
                ra[it] = *(const float4*)&A[(size_t)(m0 + a_row + it * 32) * K + k0 + a_c4];
#pragma unroll
            for (int it = 0; it < 2; it++)
                rb[it] = *(const float4*)&B[(size_t)(k0 + b_row + it * 16) * N + n0 + b_c4];
        }
#pragma unroll
        for (int kk = 0; kk < 4; kk++) {
            FragAT a[2]; FragBT b[2];
#pragma unroll
            for (int i = 0; i < 2; i++)
                wmma::load_matrix_sync(a[i], &As[cur][wm * 32 + i * 16][kk * 8], 36);
#pragma unroll
            for (int j = 0; j < 2; j++)
                wmma::load_matrix_sync(b[j], &Bs[cur][kk * 8][wn * 32 + j * 16], 68);
#pragma unroll
            for (int i = 0; i < 2; i++)
#pragma unroll
                for (int j = 0; j < 2; j++) wmma::mma_sync(acc[i][j], a[i], b[j], acc[i][j]);
        }
        if (k + 1 < nk) {
            int nxt = cur ^ 1;
#pragma unroll
            for (int it = 0; it < 4; it++) *(float4*)&As[nxt][a_row + it * 32][a_c4] = tfr4(ra[it]);
#pragma unroll
            for (int it = 0; it < 2; it++) *(float4*)&Bs[nxt][b_row + it * 16][b_c4] = tfr4(rb[it]);
        }
        __syncthreads();
    }
#pragma unroll
    for (int i = 0; i < 2; i++)
#pragma unroll
        for (int j = 0; j < 2; j++) {
            size_t co = (size_t)(m0 + wm * 32 + i * 16) * N + n0 + wn * 32 + j * 16;
            if (res) {
                FragC r;
                wmma::load_matrix_sync(r, res + co, N, wmma::mem_row_major);
#pragma unroll
                for (int e2 = 0; e2 < r.num_elements; e2++) acc[i][j].x[e2] += r.x[e2];
            }
            wmma::store_matrix_sync(C + co, acc[i][j], N, wmma::mem_row_major);
        }
}

__global__ __launch_bounds__(256, 2)
void gemm_tf32_pipe(const float* __restrict__ A, const float* __restrict__ B,
                    const float* __restrict__ res, float* __restrict__ C,
                    int N, int K) {
    extern __shared__ char smraw[];
    gemm_tf32_body(smraw, A, B, res, C, N, K, blockIdx.y * 128, blockIdx.x * 64);
}

// fused QKV projection: one launch, 48 n-tiles (32 Q + 8 K + 8 V)
__global__ __launch_bounds__(256, 2)
void qkv_tf32(const float* __restrict__ A,
              const float* __restrict__ wq, const float* __restrict__ wk,
              const float* __restrict__ wv) {
    extern __shared__ char smraw[];
    int nt = blockIdx.x;
    const float* B; float* C; int N, n0;
    if (nt < 32)      { B = wq; C = g_q; N = CH  * CHD; n0 = nt * 64; }
    else if (nt < 40) { B = wk; C = g_k; N = CKVH* CHD; n0 = (nt - 32) * 64; }
    else              { B = wv; C = g_v; N = CKVH* CHD; n0 = (nt - 40) * 64; }
    gemm_tf32_body(smraw, A, B, nullptr, C, N, CD, blockIdx.y * 128, n0);
}

// ---------------- per-head q/k rmsnorm + rope ----------------
__global__ void qknorm_rope_kernel(const float* __restrict__ cos_,
                                   const float* __restrict__ sin_,
                                   const float* __restrict__ qn_w,
                                   const float* __restrict__ kn_w) {
    int t = blockIdx.x;
    int hy = blockIdx.y;
    int d = threadIdx.x;
    float* ptr; const float* w;
    if (hy < CH) { ptr = g_q + ((size_t)t * CH + hy) * CHD;          w = qn_w; }
    else         { ptr = g_k + ((size_t)t * CKVH + (hy - CH)) * CHD; w = kn_w; }
    float v = ptr[d];
    float ss = v * v;
#pragma unroll
    for (int off = 16; off > 0; off >>= 1) ss += __shfl_xor_sync(0xffffffffu, ss, off);
    __shared__ float ws[4];
    if ((d & 31) == 0) ws[d >> 5] = ss;
    __syncthreads();
    float tot = ws[0] + ws[1] + ws[2] + ws[3];
    float nrm = v * rsqrtf(tot / (float)CHD + CEPS) * w[d];
    __shared__ float nbuf[128];
    nbuf[d] = nrm;
    __syncthreads();
    float rot = (d < 64) ? -nbuf[d + 64] : nbuf[d - 64];
    float c = cos_[(size_t)t * CHD + d];
    float s = sin_[(size_t)t * CHD + d];
    ptr[d] = nrm * c + rot * s;
}

// ================= flash attention v3.1: tf32 mma, pre-converted smem ====
constexpr int SM_ATTN = (64*132 + 32*132 + 64*36) * 4;   // 59904

__global__ void attn_kernel_mma() {
    extern __shared__ char sm[];
    float (*Qs)[132] = (float(*)[132])sm;
    float (*KVs)[132] = (float(*)[132])(sm + 64*132*4);
    float (*Ss)[36]  = (float(*)[36])(sm + (64+32)*132*4);

    int qt = blockIdx.x;
    int h  = blockIdx.y;
    int b  = blockIdx.z;
    int kvh = h / (CH / CKVH);
    int tid = threadIdx.x;
    int w = tid >> 5, lane = tid & 31;
    int gi = lane >> 2;
    int li = lane & 3;

    for (int i = tid; i < 64 * 32; i += 128) {
        int rr = i >> 5, c4 = (i & 31) * 4;
        *(float4*)&Qs[rr][c4] = tfr4(
            *(const float4*)&g_q[((size_t)(b * CS + qt * 64 + rr) * CH + h) * CHD + c4]);
    }

    float o[64];
#pragma unroll
    for (int i = 0; i < 64; i++) o[i] = 0.f;
    float m0 = -1e30f, m1 = -1e30f, l0 = 0.f, l1 = 0.f;
    const float scale = 0.088388347648318447f;
    int r0g = qt * 64 + w * 16 + gi;
    int r1g = r0g + 8;

    int jmax = 2 * qt + 1;
    for (int jt = 0; jt <= jmax; jt++) {
        __syncthreads();
        for (int i = tid; i < 32 * 32; i += 128) {
            int rr = i >> 5, c4 = (i & 31) * 4;
            *(float4*)&KVs[rr][c4] = tfr4(
                *(const float4*)&g_k[((size_t)(b * CS + jt * 32 + rr) * CKVH + kvh) * CHD + c4]);
        }
        __syncthreads();

        float sacc[4][4];
#pragma unroll
        for (int n = 0; n < 4; n++)
#pragma unroll
            for (int i = 0; i < 4; i++) sacc[n][i] = 0.f;
#pragma unroll
        for (int k8 = 0; k8 < 16; k8++) {
            unsigned int a0 = __float_as_uint(Qs[w * 16 + gi][k8 * 8 + li]);
            unsigned int a1 = __float_as_uint(Qs[w * 16 + gi + 8][k8 * 8 + li]);
            unsigned int a2 = __float_as_uint(Qs[w * 16 + gi][k8 * 8 + li + 4]);
            unsigned int a3 = __float_as_uint(Qs[w * 16 + gi + 8][k8 * 8 + li + 4]);
#pragma unroll
            for (int n = 0; n < 4; n++) {
                unsigned int b0 = __float_as_uint(KVs[n * 8 + gi][k8 * 8 + li]);
                unsigned int b1 = __float_as_uint(KVs[n * 8 + gi][k8 * 8 + li + 4]);
                mma_tf32(sacc[n], a0, a1, a2, a3, b0, b1);
            }
        }

        float lm0 = -1e30f, lm1 = -1e30f;
#pragma unroll
        for (int n = 0; n < 4; n++) {
            int c0 = jt * 32 + n * 8 + 2 * li;
#pragma unroll
            for (int i = 0; i < 2; i++) {
                float v0 = sacc[n][i] * scale;
                float v1 = sacc[n][i + 2] * scale;
                if (c0 + i > r0g) v0 = -1e30f;
                if (c0 + i > r1g) v1 = -1e30f;
                sacc[n][i] = v0; sacc[n][i + 2] = v1;
                lm0 = fmaxf(lm0, v0); lm1 = fmaxf(lm1, v1);
            }
        }
        lm0 = fmaxf(lm0, __shfl_xor_sync(0xffffffffu, lm0, 1));
        lm0 = fmaxf(lm0, __shfl_xor_sync(0xffffffffu, lm0, 2));
        lm1 = fmaxf(lm1, __shfl_xor_sync(0xffffffffu, lm1, 1));
        lm1 = fmaxf(lm1, __shfl_xor_sync(0xffffffffu, lm1, 2));
        float tm0 = fmaxf(m0, lm0), tm1 = fmaxf(m1, lm1);
        float al0 = expf(m0 - tm0), al1 = expf(m1 - tm1);
        float ls0 = 0.f, ls1 = 0.f;
#pragma unroll
        for (int n = 0; n < 4; n++) {
#pragma unroll
            for (int i = 0; i < 2; i++) {
                float p0 = expf(sacc[n][i] - tm0);
                float p1 = expf(sacc[n][i + 2] - tm1);
                sacc[n][i] = p0; sacc[n][i + 2] = p1;
                ls0 += p0; ls1 += p1;
            }
        }
        ls0 += __shfl_xor_sync(0xffffffffu, ls0, 1);
        ls0 += __shfl_xor_sync(0xffffffffu, ls0, 2);
        ls1 += __shfl_xor_sync(0xffffffffu, ls1, 1);
        ls1 += __shfl_xor_sync(0xffffffffu, ls1, 2);
        l0 = l0 * al0 + ls0;
        l1 = l1 * al1 + ls1;
        m0 = tm0; m1 = tm1;

#pragma unroll
        for (int n = 0; n < 4; n++) {
            Ss[w * 16 + gi][n * 8 + 2 * li]         = tfr(sacc[n][0]);
            Ss[w * 16 + gi][n * 8 + 2 * li + 1]     = tfr(sacc[n][1]);
            Ss[w * 16 + gi + 8][n * 8 + 2 * li]     = tfr(sacc[n][2]);
            Ss[w * 16 + gi + 8][n * 8 + 2 * li + 1] = tfr(sacc[n][3]);
        }

#pragma unroll
        for (int n = 0; n < 16; n++) {
            o[n * 4 + 0] *= al0; o[n * 4 + 1] *= al0;
            o[n * 4 + 2] *= al1; o[n * 4 + 3] *= al1;
        }

        __syncthreads();
        for (int i = tid; i < 32 * 32; i += 128) {
            int rr = i >> 5, c4 = (i & 31) * 4;
            *(float4*)&KVs[rr][c4] = tfr4(
                *(const float4*)&g_v[((size_t)(b * CS + jt * 32 + rr) * CKVH + kvh) * CHD + c4]);
        }
        __syncwarp();
        __syncthreads();

#pragma unroll
        for (int k8 = 0; k8 < 4; k8++) {
            unsigned int a0 = __float_as_uint(Ss[w * 16 + gi][k8 * 8 + li]);
            unsigned int a1 = __float_as_uint(Ss[w * 16 + gi + 8][k8 * 8 + li]);
            unsigned int a2 = __float_as_uint(Ss[w * 16 + gi][k8 * 8 + li + 4]);
            unsigned int a3 = __float_as_uint(Ss[w * 16 + gi + 8][k8 * 8 + li + 4]);
#pragma unroll
            for (int n = 0; n < 16; n++) {
                unsigned int b0 = __float_as_uint(KVs[k8 * 8 + li][n * 8 + gi]);
                unsigned int b1 = __float_as_uint(KVs[k8 * 8 + li + 4][n * 8 + gi]);
                mma_tf32(&o[n * 4], a0, a1, a2, a3, b0, b1);
            }
        }
    }

    float inv0 = 1.f / l0, inv1 = 1.f / l1;
    int t0 = b * CS + r0g, t1 = b * CS + r1g;
    float* op0 = &g_o[((size_t)t0 * CH + h) * CHD];
    float* op1 = &g_o[((size_t)t1 * CH + h) * CHD];
#pragma unroll
    for (int n = 0; n < 16; n++) {
        int col = n * 8 + 2 * li;
        float2 v0 = make_float2(o[n * 4 + 0] * inv0, o[n * 4 + 1] * inv0);
        float2 v1 = make_float2(o[n * 4 + 2] * inv1, o[n * 4 + 3] * inv1);
        *(float2*)&op0[col] = v0;
        *(float2*)&op1[col] = v1;
    }
}

// ---------------- router softmax + top-8 ----------------
__global__ void topk_kernel() {
    int t = blockIdx.x, e = threadIdx.x;
    __shared__ float red[64];
    __shared__ int   redi[64];
    __shared__ float tv[8];
    __shared__ int   ti[8];
    float lg = g_logits[t * CE + e];
    red[e] = lg; __syncthreads();
    for (int st = 32; st > 0; st >>= 1) {
        if (e < st) red[e] = fmaxf(red[e], red[e + st]);
        __syncthreads();
    }
    float mx = red[0]; __syncthreads();
    float ex = expf(lg - mx);
    red[e] = ex; __syncthreads();
    for (int st = 32; st > 0; st >>= 1) {
        if (e < st) red[e] += red[e + st];
        __syncthreads();
    }
    float sum = red[0]; __syncthreads();
    float sel = ex / sum;
    for (int k = 0; k < 8; k++) {
        red[e] = sel; redi[e] = e; __syncthreads();
        for (int st = 32; st > 0; st >>= 1) {
            if (e < st) {
                if (red[e + st] > red[e]) { red[e] = red[e + st]; redi[e] = redi[e + st]; }
            }
            __syncthreads();
        }
        if (e == 0) { tv[k] = red[0]; ti[k] = redi[0]; }
        __syncthreads();
        if (e == ti[k]) sel = -1.f;
        __syncthreads();
    }
    if (e < 8) {
        float s8 = 0.f;
#pragma unroll
        for (int k = 0; k < 8; k++) s8 += tv[k];
        g_topi[t * CK + e] = ti[e];
        g_topw[t * CK + e] = tv[e] / s8;
    }
}

// ---------------- routing bookkeeping ----------------
__global__ void zero_counts_kernel() { if (threadIdx.x < CE) g_counts[threadIdx.x] = 0; }

__global__ void count_kernel() {
    int i = blockIdx.x * blockDim.x + threadIdx.x;
    if (i < NSLOT) atomicAdd(&g_counts[g_topi[i]], 1);
}

__global__ void scan_kernel() {
    int acc = 0;
    for (int e = 0; e < CE; e++) {
        g_offsets[e] = acc;
        g_cursor[e]  = acc;
        acc += ((g_counts[e] + 127) >> 7) << 7;
    }
}

__global__ void init_slots_kernel() {
    int i = blockIdx.x * blockDim.x + threadIdx.x;
    if (i < PADTOT) g_slot_token[i] = 0;
}

__global__ void fill_kernel() {
    int i = blockIdx.x * blockDim.x + threadIdx.x;
    if (i < NSLOT) {
        int e = g_topi[i];
        int p = atomicAdd(&g_cursor[e], 1);
        g_slot_token[p] = i >> 3;
        g_pos_of[i] = p;
    }
}

// ================= unified MoE bf16 GEMM, BK=64 (R5-measured faster) =====
// MODE 0: gate = ht_bf(gather) @ w_gate -> g_gate (fp32)
// MODE 1: up   = ht_bf(gather) @ w_up; epilogue act_bf = silu(g_gate)*u
// MODE 2: down = act_bf @ w_down -> g_y (fp32)
// BM=128 BN=64 BK=64, 256 threads, double-buffered.
// smem: As bf16[2][128][72] @0 (36864) | Bs bf16[2][64][72] @36864 (18432)
//       stok int[128] @55296 (512) | scr f32[8][16][16] @55808 (8192) = 64000
constexpr int SM_MOE = 64000;

template<int MODE>
__global__ __launch_bounds__(256, 2)
void moe_gemm_bf16(const float* __restrict__ W) {
    extern __shared__ char smraw[];
    __nv_bfloat16 (*As)[128][72] = (__nv_bfloat16(*)[128][72])smraw;
    __nv_bfloat16 (*Bs)[64][72]  = (__nv_bfloat16(*)[64][72])(smraw + 36864);
    int* stok = (int*)(smraw + 55296);
    float (*scr)[16][16] = (float(*)[16][16])(smraw + 55808);

    constexpr int KDIM = (MODE == 2) ? CF : CD;
    constexpr int NDIM = (MODE == 2) ? CD : CF;

    int e = blockIdx.y;
    int n0 = blockIdx.x * 64;
    int off = g_offsets[e], cnt = g_counts[e];
    int ntiles = (cnt + 127) >> 7;
    const float* Bm = W + (size_t)e * KDIM * NDIM;

    int tid = threadIdx.x;
    int w = tid >> 5, wm = w & 3, wn = w >> 2;
    int lane = tid & 31;

    for (int rt = 0; rt < ntiles; rt++) {
        size_t abase = (size_t)(off + rt * 128);
        if (MODE < 2) {
            if (tid < 128) stok[tid] = g_slot_token[abase + tid];
            __syncthreads();
        }

        FragCB acc[2][2];
#pragma unroll
        for (int i = 0; i < 2; i++)
#pragma unroll
            for (int j = 0; j < 2; j++) wmma::fill_fragment(acc[i][j], 0.f);

        uint4 raA[4]; float4 rb[4];
        constexpr int nk = KDIM / 64;

        // prologue (k-tile 0)
#pragma unroll
        for (int it = 0; it < 4; it++) {
            int i = tid + it * 256;
            int row = i >> 3, c8 = (i & 7) * 8;
            if (MODE < 2)
                raA[it] = *(const uint4*)&g_ht_bf[(size_t)stok[row] * CD + c8];
            else
                raA[it] = *(const uint4*)&g_act_bf[(abase + row) * CF + c8];
        }
#pragma unroll
        for (int it = 0; it < 4; it++) {
            int i = tid + it * 256;
            int row = i >> 4, c4 = (i & 15) * 4;
            rb[it] = *(const float4*)&Bm[(size_t)row * NDIM + n0 + c4];
        }
#pragma unroll
        for (int it = 0; it < 4; it++) {
            int i = tid + it * 256;
            int row = i >> 3, c8 = (i & 7) * 8;
            *(uint4*)&As[0][row][c8] = raA[it];
        }
#pragma unroll
        for (int it = 0; it < 4; it++) {
            int i = tid + it * 256;
            int row = i >> 4, c4 = (i & 15) * 4;
            st_bf4(&Bs[0][row][c4], rb[it]);
        }
        __syncthreads();

        for (int k = 0; k < nk; k++) {
            int cur = k & 1;
            if (k + 1 < nk) {
                int k0 = (k + 1) * 64;
#pragma unroll
                for (int it = 0; it < 4; it++) {
                    int i = tid + it * 256;
                    int row = i >> 3, c8 = (i & 7) * 8;
                    if (MODE < 2)
                        raA[it] = *(const uint4*)&g_ht_bf[(size_t)stok[row] * CD + k0 + c8];
                    else
                        raA[it] = *(const uint4*)&g_act_bf[(abase + row) * CF + k0 + c8];
                }
#pragma unroll
                for (int it = 0; it < 4; it++) {
                    int i = tid + it * 256;
                    int row = i >> 4, c4 = (i & 15) * 4;
                    rb[it] = *(const float4*)&Bm[(size_t)(k0 + row) * NDIM + n0 + c4];
                }
            }
#pragma unroll
            for (int kk = 0; kk < 4; kk++) {
                FragAB a[2]; FragBB b[2];
#pragma unroll
                for (int i = 0; i < 2; i++)
                    wmma::load_matrix_sync(a[i], &As[cur][wm * 32 + i * 16][kk * 16], 72);
#pragma unroll
                for (int j = 0; j < 2; j++)
                    wmma::load_matrix_sync(b[j], &Bs[cur][kk * 16][wn * 32 + j * 16], 72);
#pragma unroll
                for (int i = 0; i < 2; i++)
#pragma unroll
                    for (int j = 0; j < 2; j++) wmma::mma_sync(acc[i][j], a[i], b[j], acc[i][j]);
            }
            if (k + 1 < nk) {
                int nxt = cur ^ 1;
#pragma unroll
                for (int it = 0; it < 4; it++) {
                    int i = tid + it * 256;
                    int row = i >> 3, c8 = (i & 7) * 8;
                    *(uint4*)&As[nxt][row][c8] = raA[it];
                }
#pragma unroll
                for (int it = 0; it < 4; it++) {
                    int i = tid + it * 256;
                    int row = i >> 4, c4 = (i & 15) * 4;
                    st_bf4(&Bs[nxt][row][c4], rb[it]);
                }
            }
            __syncthreads();
        }

        // epilogue
        if (MODE == 0) {
#pragma unroll
            for (int i = 0; i < 2; i++)
#pragma unroll
                for (int j = 0; j < 2; j++) {
                    float* cp = g_gate + (abase + wm * 32 + i * 16) * CF + n0 + wn * 32 + j * 16;
                    wmma::store_matrix_sync(cp, acc[i][j], CF, wmma::mem_row_major);
                }
        } else if (MODE == 2) {
#pragma unroll
            for (int i = 0; i < 2; i++)
#pragma unroll
                for (int j = 0; j < 2; j++) {
                    float* cp = g_y + (abase + wm * 32 + i * 16) * CD + n0 + wn * 32 + j * 16;
                    wmma::store_matrix_sync(cp, acc[i][j], CD, wmma::mem_row_major);
                }
        } else {
#pragma unroll
            for (int i = 0; i < 2; i++)
#pragma unroll
                for (int j = 0; j < 2; j++) {
                    wmma::store_matrix_sync(&scr[w][0][0], acc[i][j], 16, wmma::mem_row_major);
                    __syncwarp();
                    {
                        int r = lane >> 1, cb = (lane & 1) * 8;
                        size_t grow = abase + wm * 32 + i * 16 + r;
                        int col = n0 + wn * 32 + j * 16 + cb;
                        const float* gp = &g_gate[grow * CF + col];
                        float4 g0 = *(const float4*)gp;
                        float4 g1 = *(const float4*)(gp + 4);
                        float4 u0 = *(float4*)&scr[w][r][cb];
                        float4 u1 = *(float4*)&scr[w][r][cb + 4];
                        float4 o0, o1;
                        o0.x = (g0.x / (1.f + expf(-g0.x))) * u0.x;
                        o0.y = (g0.y / (1.f + expf(-g0.y))) * u0.y;
                        o0.z = (g0.z / (1.f + expf(-g0.z))) * u0.z;
                        o0.w = (g0.w / (1.f + expf(-g0.w))) * u0.w;
                        o1.x = (g1.x / (1.f + expf(-g1.x))) * u1.x;
                        o1.y = (g1.y / (1.f + expf(-g1.y))) * u1.y;
                        o1.z = (g1.z / (1.f + expf(-g1.z))) * u1.z;
                        o1.w = (g1.w / (1.f + expf(-g1.w))) * u1.w;
                        __nv_bfloat16* dst = g_act_bf + grow * CF + col;
                        st_bf4(dst, o0);
                        st_bf4(dst + 4, o1);
                    }
                    __syncwarp();
                }
        }
        __syncthreads();
    }
}

// ---------------- final combine ----------------
__global__ void final_add_kernel(float* __restrict__ out) {
    int t = blockIdx.x;
    __shared__ int   pos[8];
    __shared__ float w[8];
    if (threadIdx.x < 8) {
        pos[threadIdx.x] = g_pos_of[t * CK + threadIdx.x];
        w[threadIdx.x]   = g_topw[t * CK + threadIdx.x];
    }
    __syncthreads();
    for (int d = threadIdx.x; d < CD; d += 256) {
        float acc = out[(size_t)t * CD + d];
#pragma unroll
        for (int k = 0; k < 8; k++)
            acc += w[k] * g_y[(size_t)pos[k] * CD + d];
        out[(size_t)t * CD + d] = acc;
    }
}

// ---------------- launch ----------------
extern "C" void kernel_launch(void* const* d_in, const int* in_sizes, int n_in,
                              void* d_out, int out_size) {
    const float* x        = (const float*)d_in[0];
    const float* cos_     = (const float*)d_in[1];
    const float* sin_     = (const float*)d_in[2];
    const float* ln1_w    = (const float*)d_in[3];
    const float* wq       = (const float*)d_in[4];
    const float* wk       = (const float*)d_in[5];
    const float* wv       = (const float*)d_in[6];
    const float* wo       = (const float*)d_in[7];
    const float* qn_w     = (const float*)d_in[8];
    const float* kn_w     = (const float*)d_in[9];
    const float* ln2_w    = (const float*)d_in[10];
    const float* router_w = (const float*)d_in[11];
    const float* w_gate   = (const float*)d_in[12];
    const float* w_up     = (const float*)d_in[13];
    const float* w_down   = (const float*)d_in[14];
    float* out = (float*)d_out;

    cudaFuncSetAttribute(gemm_tf32_pipe,   cudaFuncAttributeMaxDynamicSharedMemorySize, SM_TF32);
    cudaFuncSetAttribute(qkv_tf32,         cudaFuncAttributeMaxDynamicSharedMemorySize, SM_TF32);
    cudaFuncSetAttribute(attn_kernel_mma,  cudaFuncAttributeMaxDynamicSharedMemorySize, SM_ATTN);
    cudaFuncSetAttribute(moe_gemm_bf16<0>, cudaFuncAttributeMaxDynamicSharedMemorySize, SM_MOE);
    cudaFuncSetAttribute(moe_gemm_bf16<1>, cudaFuncAttributeMaxDynamicSharedMemorySize, SM_MOE);
    cudaFuncSetAttribute(moe_gemm_bf16<2>, cudaFuncAttributeMaxDynamicSharedMemorySize, SM_MOE);

    float *p_h, *p_o, *p_ht, *p_logits;
    __nv_bfloat16 *p_ht_bf;
    cudaGetSymbolAddress((void**)&p_h,  g_h);
    cudaGetSymbolAddress((void**)&p_o,  g_o);
    cudaGetSymbolAddress((void**)&p_ht, g_ht);
    cudaGetSymbolAddress((void**)&p_ht_bf, g_ht_bf);
    cudaGetSymbolAddress((void**)&p_logits, g_logits);

    // 1. h = rmsnorm(x)
    rmsnorm_kernel<<<CT, 256>>>(x, ln1_w, p_h);
    // 2. fused q,k,v projections
    qkv_tf32<<<dim3(48, CT / 128), 256, SM_TF32>>>(p_h, wq, wk, wv);
    // 3. per-head q/k rmsnorm + rope
    qknorm_rope_kernel<<<dim3(CT, CH + CKVH), 128>>>(cos_, sin_, qn_w, kn_w);
    // 4. attention (tf32 mma, fp32 softmax)
    attn_kernel_mma<<<dim3(CS / 64, CH, CB), 128, SM_ATTN>>>();
    // 5. out = o @ wo + x
    gemm_tf32_pipe<<<dim3(CD / 64, CT / 128), 256, SM_TF32>>>(p_o, wo, x, out, CD, CD);
    // 6. ht = rmsnorm(out), fp32 + bf16
    rmsnorm_bf_kernel<<<CT, 256>>>(out, ln2_w, p_ht, p_ht_bf);
    // 7. router logits (exact fp32) + top-8
    gemm64<<<dim3(CE / 64, CT / 64), 256>>>(p_ht, router_w, nullptr, p_logits, CT, CE, CD);
    topk_kernel<<<CT, 64>>>();
    // 8. routing bookkeeping
    zero_counts_kernel<<<1, 64>>>();
    count_kernel<<<NSLOT / 256, 256>>>();
    scan_kernel<<<1, 1>>>();
    init_slots_kernel<<<PADTOT / 256, 256>>>();
    fill_kernel<<<NSLOT / 256, 256>>>();
    // 9. MoE: gate, up(+silu), down (bf16 BK=64)
    moe_gemm_bf16<0><<<dim3(CF / 64, CE), 256, SM_MOE>>>(w_gate);
    moe_gemm_bf16<1><<<dim3(CF / 64, CE), 256, SM_MOE>>>(w_up);
    moe_gemm_bf16<2><<<dim3(CD / 64, CE), 256, SM_MOE>>>(w_down);
    // 10. deterministic per-token combine
    final_add_kernel<<<CT, 256>>>(out);
}